// round 15
// baseline (speedup 1.0000x reference)
#include <cuda_runtime.h>
#include <cuda_bf16.h>
#include <math.h>
#include <stdint.h>

// ---------------------------------------------------------------------------
// GatedDeltaNet forward. tcgen05 bf16-split GEMMs (BM=256, 3-stage cp.async,
// fused qkv+g launch), chunked delta-rule recurrence (256-thread blocks,
// register-cached k/q, 16-row state slices), split stitch.
// B=2, S=2048, HID=2048, H=16, HKV=4, DK=DV=128.
// ---------------------------------------------------------------------------

#if defined(__CUDA_ARCH__) && !defined(__CUDA_ARCH_FEAT_SM103_ALL)
#define NO_TCGEN05 1
#endif

#define BS_TOTAL 4096
#define HID 2048
#define QKVD 3072
#define NH 16
#define KSPLIT 6144
#define NCHUNK 16
#define CLEN 128
#define NFUSED 5120          // QKVD + HID

// ---------------- scratch (device globals; no runtime allocation) ----------
__device__ float g_qkv [ (size_t)BS_TOTAL * QKVD ];
__device__ float g_conv[ (size_t)BS_TOTAL * QKVD ];
__device__ float g_gbuf[ (size_t)BS_TOTAL * HID  ];
__device__ float g_omid[ (size_t)BS_TOTAL * HID  ];
__device__ float g_alpha[ BS_TOTAL * NH ];
__device__ float g_beta [ BS_TOTAL * NH ];
__device__ float g_qt  [ (size_t)32 * 2048 * 128 ];
__device__ float g_G   [ (size_t)32 * NCHUNK * 128 * 128 ];
__device__ float g_B   [ (size_t)32 * NCHUNK * 128 * 128 ];
__device__ float g_Sst [ (size_t)32 * 15 * 4 * 4096 ];
__device__ __nv_bfloat16 g_a3x [ (size_t)BS_TOTAL * KSPLIT ];
__device__ __nv_bfloat16 g_a3o [ (size_t)BS_TOTAL * KSPLIT ];
__device__ __nv_bfloat16 g_b3a [ (size_t)NFUSED   * KSPLIT ];
__device__ __nv_bfloat16 g_b3o [ (size_t)HID      * KSPLIT ];

// ---------------- f32x2 packed helpers -------------------------------------
__device__ __forceinline__ unsigned long long pk2(float lo, float hi) {
    unsigned long long r;
    asm("mov.b64 %0, {%1, %2};" : "=l"(r)
        : "r"(__float_as_uint(lo)), "r"(__float_as_uint(hi)));
    return r;
}
__device__ __forceinline__ void up2(unsigned long long v, float& lo, float& hi) {
    unsigned int a, b;
    asm("mov.b64 {%0, %1}, %2;" : "=r"(a), "=r"(b) : "l"(v));
    lo = __uint_as_float(a); hi = __uint_as_float(b);
}
__device__ __forceinline__ unsigned long long fma2(unsigned long long a,
                                                   unsigned long long b,
                                                   unsigned long long c) {
    unsigned long long d;
    asm("fma.rn.f32x2 %0, %1, %2, %3;" : "=l"(d) : "l"(a), "l"(b), "l"(c));
    return d;
}
__device__ __forceinline__ unsigned long long mul2(unsigned long long a,
                                                   unsigned long long b) {
    unsigned long long d;
    asm("mul.rn.f32x2 %0, %1, %2;" : "=l"(d) : "l"(a), "l"(b));
    return d;
}

// ---------------- common helpers -------------------------------------------
__device__ __forceinline__ uint32_t smem_u32(const void* p) {
    uint32_t a;
    asm("{ .reg .u64 t; cvta.to.shared.u64 t, %1; cvt.u32.u64 %0, t; }"
        : "=r"(a) : "l"(p));
    return a;
}

#define SW128(o) ((o) ^ (((o) >> 3) & 0x70))

#define CP_ASYNC16(sa, g) \
    asm volatile("cp.async.cg.shared.global [%0], [%1], 16;" \
                 :: "r"(sa), "l"(g) : "memory")
#define CP_COMMIT() asm volatile("cp.async.commit_group;" ::: "memory")
#define CP_WAIT(n)  asm volatile("cp.async.wait_group %0;" :: "n"(n) : "memory")

#ifndef NO_TCGEN05
__device__ __forceinline__ bool elect1() {
    uint32_t p;
    asm volatile("{ .reg .pred p; elect.sync _|p, 0xFFFFFFFF; selp.b32 %0,1,0,p; }"
                 : "=r"(p));
    return p != 0;
}
#define MBAR_INIT(a, c) \
    asm volatile("mbarrier.init.shared.b64 [%0], %1;" :: "r"(a), "r"(c) : "memory")
#define MBAR_WAIT(a, ph) do {                                                   \
    uint32_t _m = (a); uint32_t _p = (ph); uint32_t _d;                         \
    asm volatile("{\n\t.reg .pred p;\n\t"                                       \
        "mbarrier.try_wait.parity.acquire.cta.shared::cta.b64 p, [%1], %2;\n\t" \
        "selp.b32 %0, 1, 0, p;\n\t}"                                            \
        : "=r"(_d) : "r"(_m), "r"(_p) : "memory");                              \
    if (!_d) {                                                                  \
        asm volatile("{\n\t.reg .pred P1;\n\t"                                  \
            "WL_%=:\n\t"                                                        \
            "mbarrier.try_wait.parity.acquire.cta.shared::cta.b64 P1, [%0], %1, 0x989680;\n\t" \
            "@P1 bra.uni WD_%=;\n\t"                                            \
            "bra.uni WL_%=;\n\t"                                                \
            "WD_%=:\n\t}"                                                       \
            :: "r"(_m), "r"(_p) : "memory");                                    \
    }                                                                           \
} while (0)

#define TM_ALLOC(sa, n) \
    asm volatile("tcgen05.alloc.cta_group::1.sync.aligned.shared::cta.b32 [%0], %1;" \
                 :: "r"(sa), "r"(n) : "memory")
#define TM_DEALLOC(t, n) \
    asm volatile("tcgen05.dealloc.cta_group::1.sync.aligned.b32 %0, %1;" :: "r"(t), "r"(n))
#define TM_COMMIT(mb) \
    asm volatile("tcgen05.commit.cta_group::1.mbarrier::arrive::one.shared::cluster.b64 [%0];" \
                 :: "r"(mb) : "memory")
#define FENCE_ASYNC() asm volatile("fence.proxy.async.shared::cta;" ::: "memory")
#define TM_FENCE_AFTER() asm volatile("tcgen05.fence::after_thread_sync;" ::: "memory")
#define TM_WAIT_LD() asm volatile("tcgen05.wait::ld.sync.aligned;" ::: "memory")

__device__ __forceinline__ void mma_f16_ss(uint32_t d, uint64_t ad, uint64_t bd,
                                           uint32_t idesc, bool acc) {
    uint32_t en = acc ? 1u : 0u, z = 0u;
    asm volatile("{\n\t.reg .pred p;\n\tsetp.ne.u32 p, %5, 0;\n\t"
        "tcgen05.mma.cta_group::1.kind::f16 [%0], %1, %2, %3, {%4, %4, %4, %4}, p;\n\t}"
        :: "r"(d), "l"(ad), "l"(bd), "r"(idesc), "r"(z), "r"(en) : "memory");
}

#define LDTM_X32(r, a) \
    asm volatile("tcgen05.ld.sync.aligned.32x32b.x32.b32 "                      \
        "{%0, %1, %2, %3, %4, %5, %6, %7, "                                     \
        " %8, %9, %10, %11, %12, %13, %14, %15, "                               \
        " %16, %17, %18, %19, %20, %21, %22, %23, "                             \
        " %24, %25, %26, %27, %28, %29, %30, %31}, [%32];"                      \
        : "=r"((r)[0]),  "=r"((r)[1]),  "=r"((r)[2]),  "=r"((r)[3]),            \
          "=r"((r)[4]),  "=r"((r)[5]),  "=r"((r)[6]),  "=r"((r)[7]),            \
          "=r"((r)[8]),  "=r"((r)[9]),  "=r"((r)[10]), "=r"((r)[11]),           \
          "=r"((r)[12]), "=r"((r)[13]), "=r"((r)[14]), "=r"((r)[15]),           \
          "=r"((r)[16]), "=r"((r)[17]), "=r"((r)[18]), "=r"((r)[19]),           \
          "=r"((r)[20]), "=r"((r)[21]), "=r"((r)[22]), "=r"((r)[23]),           \
          "=r"((r)[24]), "=r"((r)[25]), "=r"((r)[26]), "=r"((r)[27]),           \
          "=r"((r)[28]), "=r"((r)[29]), "=r"((r)[30]), "=r"((r)[31])            \
        : "r"(a))
#endif // !NO_TCGEN05

// ---------------------------------------------------------------------------
// Split conversion helper.
// ---------------------------------------------------------------------------
__device__ __forceinline__ void split_row4(const float* in, __nv_bfloat16* out,
                                           int idx, int mode)
{
    int r = idx >> 9, c4 = idx & 511;
    float4 v = ((const float4*)in)[idx];
    __nv_bfloat16 h0 = __float2bfloat16_rn(v.x);
    __nv_bfloat16 h1 = __float2bfloat16_rn(v.y);
    __nv_bfloat16 h2 = __float2bfloat16_rn(v.z);
    __nv_bfloat16 h3 = __float2bfloat16_rn(v.w);
    __nv_bfloat16 l0 = __float2bfloat16_rn(v.x - __bfloat162float(h0));
    __nv_bfloat16 l1 = __float2bfloat16_rn(v.y - __bfloat162float(h1));
    __nv_bfloat16 l2 = __float2bfloat16_rn(v.z - __bfloat162float(h2));
    __nv_bfloat16 l3 = __float2bfloat16_rn(v.w - __bfloat162float(h3));
    uint2 hv, lv;
    hv.x = (uint32_t)__bfloat16_as_ushort(h0) | ((uint32_t)__bfloat16_as_ushort(h1) << 16);
    hv.y = (uint32_t)__bfloat16_as_ushort(h2) | ((uint32_t)__bfloat16_as_ushort(h3) << 16);
    lv.x = (uint32_t)__bfloat16_as_ushort(l0) | ((uint32_t)__bfloat16_as_ushort(l1) << 16);
    lv.y = (uint32_t)__bfloat16_as_ushort(l2) | ((uint32_t)__bfloat16_as_ushort(l3) << 16);
    size_t base = (size_t)r * KSPLIT + c4 * 4;
    *(uint2*)&out[base] = hv;
    if (mode == 0) {
        *(uint2*)&out[base + 2048] = hv;
        *(uint2*)&out[base + 4096] = lv;
    } else {
        *(uint2*)&out[base + 2048] = lv;
        *(uint2*)&out[base + 4096] = hv;
    }
}

__global__ void __launch_bounds__(256)
convert_all(const float* __restrict__ x, __nv_bfloat16* __restrict__ ax,
            const float* __restrict__ qkvw, __nv_bfloat16* __restrict__ bq,
            const float* __restrict__ gw, __nv_bfloat16* __restrict__ bg,
            const float* __restrict__ ow, __nv_bfloat16* __restrict__ bo)
{
    int idx = blockIdx.x * 256 + threadIdx.x;
    if (idx < BS_TOTAL * 512) {
        split_row4(x, ax, idx, 0);
        return;
    }
    idx -= BS_TOTAL * 512;
    if (idx < QKVD * 512)
        split_row4(qkvw, bq, idx, 1);
    else if (idx < (QKVD + HID) * 512)
        split_row4(gw, bg, idx - QKVD * 512, 1);
    else if (idx < (QKVD + 2 * HID) * 512)
        split_row4(ow, bo, idx - (QKVD + HID) * 512, 1);
}

__global__ void __launch_bounds__(256)
convert_split(const float* __restrict__ in, __nv_bfloat16* __restrict__ out,
              int total4, int mode)
{
    int idx = blockIdx.x * 256 + threadIdx.x;
    if (idx < total4) split_row4(in, out, idx, mode);
}

// ---------------------------------------------------------------------------
// Main GEMM: BM=256, BN=256, BK=64, 3-stage cp.async, 1 CTA/SM.
// ---------------------------------------------------------------------------
#define BM 256
#define BN 256
#define BK 64
#define NSTAGE 3
#define STAGE_BYTES 65536
#define GEMM_SMEM (1024 + NSTAGE*STAGE_BYTES)

__global__ void __launch_bounds__(256, 1) __cluster_dims__(1, 1, 1)
gemm_main(const __nv_bfloat16* __restrict__ A3, const __nv_bfloat16* __restrict__ B3,
          const float* __restrict__ Af, const float* __restrict__ Bf,
          float* __restrict__ C, float* __restrict__ C2,
          int M, int N, int K3, int Kf, int Nsplit)
{
    extern __shared__ char smem[];
#ifndef NO_TCGEN05
    const uint32_t sbase = smem_u32(smem);
    const int tid = threadIdx.x;
    const int wid = tid >> 5, lane = tid & 31;
    const int bm = blockIdx.y * BM, bn = blockIdx.x * BN;

    const uint32_t IDESC =
        (1u << 4) | (1u << 7) | (1u << 10) | ((BN / 8) << 17) | ((128 / 16) << 24);
    const unsigned long long DESC_BASE =
        (2ull << 61) | (1ull << 46) | (64ull << 32) | (1ull << 16);

    if (wid == 0) TM_ALLOC(sbase + 0, 512);
    if (tid == 0) {
        MBAR_INIT(sbase + 8, 1);  MBAR_INIT(sbase + 16, 1);
        MBAR_INIT(sbase + 24, 1);
    }
    __syncthreads();
    uint32_t tmem;
    asm volatile("ld.shared.b32 %0, [%1];" : "=r"(tmem) : "r"(sbase + 0));

    const int NK = K3 / BK;
    const __nv_bfloat16* Ab = A3 + (size_t)bm * K3;
    const __nv_bfloat16* Bb = B3 + (size_t)bn * K3;

    auto load_stage = [&](int kt, int s) {
        const uint32_t sa = sbase + 1024 + s * STAGE_BYTES;
        const __nv_bfloat16* Ak = Ab + (size_t)kt * BK;
#pragma unroll
        for (int i = 0; i < 8; i++) {
            int chunk = tid + 256 * i;
            int row = chunk >> 3, c = chunk & 7;
            CP_ASYNC16(sa + SW128(row * 128 + c * 16),
                       Ak + (size_t)row * K3 + c * 8);
        }
        const __nv_bfloat16* Bk = Bb + (size_t)kt * BK;
        const uint32_t sb = sa + 32768;
#pragma unroll
        for (int i = 0; i < 8; i++) {
            int chunk = tid + 256 * i;
            int row = chunk >> 3, c = chunk & 7;
            CP_ASYNC16(sb + SW128(row * 128 + c * 16),
                       Bk + (size_t)row * K3 + c * 8);
        }
    };

    load_stage(0, 0); CP_COMMIT();
    load_stage(1, 1); CP_COMMIT();

    int ph[NSTAGE] = {0, 0, 0};
    int sidx = 0;
    for (int kt = 0; kt < NK; kt++) {
        const int s = sidx;
        CP_WAIT(1);
        __syncthreads();
        if (wid == 0) {
            FENCE_ASYNC();
            if (elect1()) {
                const uint32_t st = sbase + 1024 + s * STAGE_BYTES;
                uint64_t ad = DESC_BASE | ((st >> 4) & 0x3FFF);
                uint64_t bd = DESC_BASE | (((st + 32768) >> 4) & 0x3FFF);
#pragma unroll
                for (int half = 0; half < 2; half++)
#pragma unroll
                    for (int kc = 0; kc < 4; kc++)
                        mma_f16_ss(tmem + half * 256,
                                   ad + half * 1024 + kc * 2, bd + kc * 2,
                                   IDESC, (kt > 0) || (kc > 0));
                TM_COMMIT(sbase + 8 + s * 8);
            }
        }
        const int kn = kt + 2;
        if (kn < NK) {
            int sp = s + 2; if (sp >= NSTAGE) sp -= NSTAGE;
            if (kt >= 1) {
                MBAR_WAIT(sbase + 8 + sp * 8, ph[sp]);
                ph[sp] ^= 1;
            }
            load_stage(kn, sp);
            CP_COMMIT();
        }
        sidx = s + 1; if (sidx >= NSTAGE) sidx -= NSTAGE;
    }
    {
        int sl = (NK - 1) % NSTAGE;
        MBAR_WAIT(sbase + 8 + sl * 8, ph[sl]);
    }
    TM_FENCE_AFTER();

    {
        const int sub = wid & 3, half = wid >> 2;
        const int gc0 = bn + half * 128;
        float* base; int ld, coff;
        if (gc0 < Nsplit) { base = C;  ld = Nsplit;     coff = gc0; }
        else              { base = C2; ld = N - Nsplit; coff = gc0 - Nsplit; }
#pragma unroll
        for (int mh = 0; mh < 2; mh++) {
            const int row = bm + mh * 128 + sub * 32 + lane;
            float* crow = base + (size_t)row * ld + coff;
#pragma unroll
            for (int cb = 0; cb < 4; cb++) {
                uint32_t r[32];
                LDTM_X32(r, tmem + mh * 256 + half * 128 + cb * 32);
                TM_WAIT_LD();
#pragma unroll
                for (int j = 0; j < 8; j++) {
                    float4 o = make_float4(__uint_as_float(r[4 * j + 0]),
                                           __uint_as_float(r[4 * j + 1]),
                                           __uint_as_float(r[4 * j + 2]),
                                           __uint_as_float(r[4 * j + 3]));
                    *(float4*)(crow + cb * 32 + 4 * j) = o;
                }
            }
        }
    }
    __syncthreads();
    if (wid == 0) TM_DEALLOC(tmem, 512);

#else  // ---------------- fp32 f32x2 fallback (non-'a' pass) ----------------
    float* As = (float*)smem;
    float* Bs = As + 2 * 16 * 132;
    const int tid = threadIdx.x;
    const int tx = tid & 15, ty = tid >> 4;
    const int lr = tid >> 2, lk = (tid & 3) * 4;
    const int K = Kf;
    const size_t rowK64 = (size_t)64 * K;

    for (int sub = 0; sub < 4; sub++) {
        const int bm = blockIdx.y * BM + (sub >> 1) * 128;
        const int bn = blockIdx.x * BN + (sub & 1) * 128;
        const float* Aptr = Af + (size_t)(bm + lr) * K + lk;
        const float* Bptr = Bf + (size_t)(bn + lr) * K + lk;
        float* cbase; int ld, coff;
        if (bn < Nsplit) { cbase = C;  ld = Nsplit;     coff = bn; }
        else             { cbase = C2; ld = N - Nsplit; coff = bn - Nsplit; }

        unsigned long long acc[8][4];
#pragma unroll
        for (int i = 0; i < 8; i++)
#pragma unroll
            for (int j = 0; j < 4; j++) acc[i][j] = 0ull;

        float4 a0 = *(const float4*)(Aptr);
        float4 a1 = *(const float4*)(Aptr + rowK64);
        float4 b0 = *(const float4*)(Bptr);
        float4 b1 = *(const float4*)(Bptr + rowK64);
        int buf = 0;
#define AS(b,k,i) As[((b)*16 + (k)) * 132 + (i)]
#define BS(b,k,i) Bs[((b)*16 + (k)) * 132 + (i)]
        AS(buf,lk+0,lr)=a0.x; AS(buf,lk+1,lr)=a0.y; AS(buf,lk+2,lr)=a0.z; AS(buf,lk+3,lr)=a0.w;
        AS(buf,lk+0,lr+64)=a1.x; AS(buf,lk+1,lr+64)=a1.y; AS(buf,lk+2,lr+64)=a1.z; AS(buf,lk+3,lr+64)=a1.w;
        BS(buf,lk+0,lr)=b0.x; BS(buf,lk+1,lr)=b0.y; BS(buf,lk+2,lr)=b0.z; BS(buf,lk+3,lr)=b0.w;
        BS(buf,lk+0,lr+64)=b1.x; BS(buf,lk+1,lr+64)=b1.y; BS(buf,lk+2,lr+64)=b1.z; BS(buf,lk+3,lr+64)=b1.w;
        __syncthreads();

        const int nk = K >> 4;
        for (int kt = 0; kt < nk; kt++) {
            const bool hasNext = (kt + 1) < nk;
            float4 na0, na1, nb0, nb1;
            if (hasNext) {
                const float* Ap = Aptr + (size_t)(kt + 1) * 16;
                const float* Bp = Bptr + (size_t)(kt + 1) * 16;
                na0 = *(const float4*)(Ap);  na1 = *(const float4*)(Ap + rowK64);
                nb0 = *(const float4*)(Bp);  nb1 = *(const float4*)(Bp + rowK64);
            }
#pragma unroll
            for (int kk = 0; kk < 16; kk++) {
                float4 af0 = *(const float4*)&AS(buf, kk, ty * 8);
                float4 af1 = *(const float4*)&AS(buf, kk, ty * 8 + 4);
                ulonglong2 bp0 = *(const ulonglong2*)&BS(buf, kk, tx * 8);
                ulonglong2 bp1 = *(const ulonglong2*)&BS(buf, kk, tx * 8 + 4);
                unsigned long long bb[4] = { bp0.x, bp0.y, bp1.x, bp1.y };
                unsigned long long a2[8];
                a2[0]=pk2(af0.x,af0.x); a2[1]=pk2(af0.y,af0.y);
                a2[2]=pk2(af0.z,af0.z); a2[3]=pk2(af0.w,af0.w);
                a2[4]=pk2(af1.x,af1.x); a2[5]=pk2(af1.y,af1.y);
                a2[6]=pk2(af1.z,af1.z); a2[7]=pk2(af1.w,af1.w);
#pragma unroll
                for (int i = 0; i < 8; i++) {
                    acc[i][0] = fma2(a2[i], bb[0], acc[i][0]);
                    acc[i][1] = fma2(a2[i], bb[1], acc[i][1]);
                    acc[i][2] = fma2(a2[i], bb[2], acc[i][2]);
                    acc[i][3] = fma2(a2[i], bb[3], acc[i][3]);
                }
            }
            if (hasNext) {
                buf ^= 1;
                __syncthreads();
                AS(buf,lk+0,lr)=na0.x; AS(buf,lk+1,lr)=na0.y; AS(buf,lk+2,lr)=na0.z; AS(buf,lk+3,lr)=na0.w;
                AS(buf,lk+0,lr+64)=na1.x; AS(buf,lk+1,lr+64)=na1.y; AS(buf,lk+2,lr+64)=na1.z; AS(buf,lk+3,lr+64)=na1.w;
                BS(buf,lk+0,lr)=nb0.x; BS(buf,lk+1,lr)=nb0.y; BS(buf,lk+2,lr)=nb0.z; BS(buf,lk+3,lr)=nb0.w;
                BS(buf,lk+0,lr+64)=nb1.x; BS(buf,lk+1,lr+64)=nb1.y; BS(buf,lk+2,lr+64)=nb1.z; BS(buf,lk+3,lr+64)=nb1.w;
                __syncthreads();
            }
        }
#undef AS
#undef BS
#pragma unroll
        for (int i = 0; i < 8; i++) {
            float r0,r1,r2,r3,r4,r5,r6,r7;
            up2(acc[i][0],r0,r1); up2(acc[i][1],r2,r3);
            up2(acc[i][2],r4,r5); up2(acc[i][3],r6,r7);
            float* cp = cbase + (size_t)(bm + ty * 8 + i) * ld + coff + tx * 8;
            *(float4*)(cp)     = make_float4(r0,r1,r2,r3);
            *(float4*)(cp + 4) = make_float4(r4,r5,r6,r7);
        }
        __syncthreads();
    }
#endif
}

// ---------------------------------------------------------------------------
// Causal depthwise conv (K=4) + SiLU + per-head l2norm (static smem).
// ---------------------------------------------------------------------------
__global__ void __launch_bounds__(256)
conv_norm_kernel(const float* __restrict__ qkv, const float* __restrict__ cw,
                 float* __restrict__ out)
{
    const int bs = blockIdx.x;
    const int b = bs >> 11, s = bs & 2047;
    __shared__ float buf[QKVD];
    __shared__ float sc[20];
    const size_t rowbase = (size_t)bs * QKVD;

    for (int c = threadIdx.x; c < QKVD; c += 256) {
        float acc = 0.f;
#pragma unroll
        for (int i = 0; i < 4; i++) {
            int sp = s - 3 + i;
            if (sp >= 0)
                acc += cw[c * 4 + i] * qkv[((size_t)(b * 2048 + sp)) * QKVD + c];
        }
        buf[c] = acc / (1.f + expf(-acc));
    }
    __syncthreads();

    const int w = threadIdx.x >> 5, lane = threadIdx.x & 31;
    for (int hd = w; hd < 20; hd += 8) {
        const int base = (hd < 16) ? hd * 128 : 2048 + (hd - 16) * 128;
        float ss = 0.f;
#pragma unroll
        for (int j = 0; j < 4; j++) {
            float x = buf[base + lane + 32 * j];
            ss += x * x;
        }
#pragma unroll
        for (int m = 16; m; m >>= 1) ss += __shfl_xor_sync(0xffffffffu, ss, m);
        if (lane == 0) {
            float r = rsqrtf(ss + 1e-6f);
            sc[hd] = (hd < 16) ? r * 0.08838834764831845f : r;
        }
    }
    __syncthreads();

    for (int c = threadIdx.x; c < QKVD; c += 256) {
        float scale = (c < 2048) ? sc[c >> 7]
                    : (c < 2560) ? sc[16 + ((c - 2048) >> 7)]
                                 : 1.f;
        out[rowbase + c] = buf[c] * scale;
    }
}

// ---------------------------------------------------------------------------
// alpha/beta projections, 4 bs-rows per block (static smem).
// ---------------------------------------------------------------------------
__global__ void __launch_bounds__(256)
proj_ab_kernel(const float* __restrict__ x, const float* __restrict__ gkw,
               const float* __restrict__ bw, float* __restrict__ alpha,
               float* __restrict__ beta)
{
    const int bs0 = blockIdx.x * 4;
    __shared__ __align__(16) float xs[4][HID];
    for (int i = threadIdx.x * 4; i < 4 * HID; i += 256 * 4) {
        int r = i >> 11, c = i & (HID - 1);
        *(float4*)&xs[r][c] = *(const float4*)&x[(size_t)(bs0 + r) * HID + c];
    }
    __syncthreads();

    const int w = threadIdx.x >> 5, lane = threadIdx.x & 31;
    for (int out = w; out < 32; out += 8) {
        const float* wr = (out < 16) ? gkw + (size_t)out * HID
                                     : bw + (size_t)(out - 16) * HID;
        const float4* w4 = (const float4*)wr;
        float acc0 = 0.f, acc1 = 0.f, acc2 = 0.f, acc3 = 0.f;
#pragma unroll 4
        for (int j = 0; j < 16; j++) {
            float4 q = w4[lane + 32 * j];
            float4 a0 = ((const float4*)xs[0])[lane + 32 * j];
            float4 a1 = ((const float4*)xs[1])[lane + 32 * j];
            float4 a2 = ((const float4*)xs[2])[lane + 32 * j];
            float4 a3 = ((const float4*)xs[3])[lane + 32 * j];
            acc0 += a0.x*q.x + a0.y*q.y + a0.z*q.z + a0.w*q.w;
            acc1 += a1.x*q.x + a1.y*q.y + a1.z*q.z + a1.w*q.w;
            acc2 += a2.x*q.x + a2.y*q.y + a2.z*q.z + a2.w*q.w;
            acc3 += a3.x*q.x + a3.y*q.y + a3.z*q.z + a3.w*q.w;
        }
#pragma unroll
        for (int m = 16; m; m >>= 1) {
            acc0 += __shfl_down_sync(0xffffffffu, acc0, m);
            acc1 += __shfl_down_sync(0xffffffffu, acc1, m);
            acc2 += __shfl_down_sync(0xffffffffu, acc2, m);
            acc3 += __shfl_down_sync(0xffffffffu, acc3, m);
        }
        if (lane == 0) {
            float accs[4] = {acc0, acc1, acc2, acc3};
#pragma unroll
            for (int r = 0; r < 4; r++) {
                float p = accs[r];
                int bs = bs0 + r;
                if (out < 16) {
                    float ls = fminf(p, 0.f) - log1pf(expf(-fabsf(p)));
                    alpha[bs * NH + out] = expf(ls * 0.0625f);
                } else {
                    beta[bs * NH + (out - 16)] = 1.f / (1.f + expf(-p));
                }
            }
        }
    }
}

// ---------------------------------------------------------------------------
// Chunked delta recurrence, phase 1. 256 threads: thread t -> col cq=t>>3,
// rowgroup rg=t&7 (16 rows, 8 ull of S and G). k/q register-cached per step.
// Padded smem: element e at (e>>4)*18 + (e&15); rowgroup stride 18 floats
// (9 ull) -> LDS.64 banks 2i + {0,18,4,22,8,26,12,30} mod 32: conflict-free.
// Threads 0-127 stage k, 128-255 stage q. Reductions: 3 shfl (8 lanes).
// Dead-work pruning: ck==0 skips G/qt; ck==15 skips G/B stores.
// ---------------------------------------------------------------------------
__global__ void __launch_bounds__(256)
recur_chunk_kernel(const float* __restrict__ conv, const float* __restrict__ alpha,
                   const float* __restrict__ beta, float* __restrict__ omid,
                   float* __restrict__ qt, float* __restrict__ Gout,
                   float* __restrict__ Bout)
{
    const int cg = blockIdx.x;
    const int ck = blockIdx.y;
    const int bh = blockIdx.z;
    const int b = bh >> 4, h = bh & 15;
    const int t = threadIdx.x;
    const int cq = t >> 3, rg = t & 7;
    const int col = cg * 32 + cq;
    const int kh = h >> 2;
    const bool needG = (ck != 0);
    const int e = t & 127;                         // element this thread stages
    const int which = t >> 7;                      // 0 = k, 1 = q
    const int woff = ((e >> 4) * 18) + (e & 15);   // padded offset

    __shared__ __align__(16) float kqf[4][2][144];

    unsigned long long S2[8], G2[8];
#pragma unroll
    for (int i = 0; i < 8; i++) {
        S2[i] = 0ull;
        int r0 = rg * 16 + 2 * i;
        G2[i] = pk2((r0 == col) ? 1.f : 0.f, (r0 + 1 == col) ? 1.f : 0.f);
    }

    const int s0g = ck * CLEN;
    const size_t bb0 = (size_t)b * 2048 * QKVD;
    const float* qc = conv + bb0 + (size_t)s0g * QKVD + h * 128;
    const float* kc = conv + bb0 + (size_t)s0g * QKVD + 2048 + kh * 128;
    const float* vc = conv + bb0 + (size_t)s0g * QKVD + 2560 + kh * 128 + col;
    const float* abase = alpha + (size_t)(b * 2048 + s0g) * NH + h;
    const float* bbase = beta  + (size_t)(b * 2048 + s0g) * NH + h;
    float* obase  = omid + (size_t)(b * 2048 + s0g) * HID + h * 128;
    float* qtbase = qt + ((size_t)bh * 2048 + s0g) * 128;

    // per-thread staging stream: k element e (which=0) or q element e (which=1)
    const float* stage_src = which ? (qc + e) : (kc + e);
    kqf[0][which][woff] = stage_src[0];
    float st_next = stage_src[QKVD];
    float vA = vc[0],  vB = vc[QKVD];
    float aA = abase[0], aB = abase[NH];
    float bA = bbase[0], bB = bbase[NH];
    __syncthreads();

    for (int s = 0; s < CLEN; s++) {
        kqf[(s + 1) & 3][which][woff] = st_next;
        const int sn = (s + 2 < CLEN) ? s + 2 : CLEN - 1;
        st_next = stage_src[(size_t)sn * QKVD];
        float vN = vc[(size_t)sn * QKVD];
        float aN = abase[sn * NH];
        float bN = bbase[sn * NH];
        __syncthreads();

        // register-cache this step's k and q slices (one LDS pass)
        const unsigned long long* k2 =
            (const unsigned long long*)kqf[s & 3][0] + rg * 9;
        const unsigned long long* q2 =
            (const unsigned long long*)kqf[s & 3][1] + rg * 9;
        unsigned long long kr[8], qr[8];
#pragma unroll
        for (int i = 0; i < 8; i++) { kr[i] = k2[i]; qr[i] = q2[i]; }
        const unsigned long long a2 = pk2(aA, aA);

        if (needG) {
            unsigned long long uA = 0ull;
#pragma unroll
            for (int i = 0; i < 8; i++) uA = fma2(kr[i], G2[i], uA);
            float ux, uy; up2(uA, ux, uy);
            float u = ux + uy;
            u += __shfl_xor_sync(0xffffffffu, u, 1);
            u += __shfl_xor_sync(0xffffffffu, u, 2);
            u += __shfl_xor_sync(0xffffffffu, u, 4);
            const float w = aA * bA * u;
            const unsigned long long w2 = pk2(-w, -w);
            unsigned long long qacc = 0ull;
#pragma unroll
            for (int i = 0; i < 8; i++) {
                unsigned long long g = mul2(G2[i], a2);
                g = fma2(kr[i], w2, g);
                G2[i] = g;
                qacc = fma2(qr[i], g, qacc);
            }
            float qx, qy; up2(qacc, qx, qy);
            float qtv = qx + qy;
            qtv += __shfl_xor_sync(0xffffffffu, qtv, 1);
            qtv += __shfl_xor_sync(0xffffffffu, qtv, 2);
            qtv += __shfl_xor_sync(0xffffffffu, qtv, 4);
            if (rg == 0) qtbase[(size_t)s * 128 + col] = qtv;
        }

        unsigned long long vpA = 0ull;
#pragma unroll
        for (int i = 0; i < 8; i++) {
            unsigned long long sv = mul2(S2[i], a2);
            vpA = fma2(kr[i], sv, vpA);
            S2[i] = sv;
        }
        float px, py; up2(vpA, px, py);
        float vp = px + py;
        vp += __shfl_xor_sync(0xffffffffu, vp, 1);
        vp += __shfl_xor_sync(0xffffffffu, vp, 2);
        vp += __shfl_xor_sync(0xffffffffu, vp, 4);
        const float delta = (vA - vp) * bA;
        const unsigned long long d2 = pk2(delta, delta);

        unsigned long long oacc = 0ull;
#pragma unroll
        for (int i = 0; i < 8; i++) {
            unsigned long long sv = fma2(kr[i], d2, S2[i]);
            S2[i] = sv;
            oacc = fma2(qr[i], sv, oacc);
        }
        float ox, oy; up2(oacc, ox, oy);
        float osum = ox + oy;
        osum += __shfl_xor_sync(0xffffffffu, osum, 1);
        osum += __shfl_xor_sync(0xffffffffu, osum, 2);
        osum += __shfl_xor_sync(0xffffffffu, osum, 4);
        if (rg == 0) obase[(size_t)s * HID + col] = osum;

        vA = vB; vB = vN;
        aA = aB; aB = aN;
        bA = bB; bB = bN;
    }

    if (ck <= 14) {
        float* Bp = Bout + ((size_t)bh * NCHUNK + ck) * 16384;
#pragma unroll
        for (int i = 0; i < 8; i++) {
            int r0 = rg * 16 + 2 * i;
            float s0v, s1v; up2(S2[i], s0v, s1v);
            Bp[(size_t)r0 * 128 + col]       = s0v;
            Bp[(size_t)(r0 + 1) * 128 + col] = s1v;
        }
        if (needG) {
            float* Gp = Gout + ((size_t)bh * NCHUNK + ck) * 16384;
#pragma unroll
            for (int i = 0; i < 8; i++) {
                int r0 = rg * 16 + 2 * i;
                float g0, g1; up2(G2[i], g0, g1);
                Gp[(size_t)r0 * 128 + col]       = g0;
                Gp[(size_t)(r0 + 1) * 128 + col] = g1;
            }
        }
    }
}

// ---------------------------------------------------------------------------
// Stitch A: serial S_start chain. Grid (4 cg, 32 bh), 256 thr.
// ---------------------------------------------------------------------------
#define CHAIN_SMEM (128*33*4 + 128*130*4)

__global__ void __launch_bounds__(256)
stitch_chain_kernel(const float* __restrict__ Gin, const float* __restrict__ Bin,
                    float* __restrict__ Sst)
{
    extern __shared__ float sm[];
    float* Ssm = sm;
    float* Tg  = sm + 128 * 33;
    const int cg = blockIdx.x, bh = blockIdx.y;
    const int t = threadIdx.x;
    const int tc = t & 15, tr = t >> 4;
    const int c0 = 2 * tc;
    const size_t gb0 = (size_t)bh * NCHUNK * 16384;

    for (int i = t; i < 4096; i += 256) {
        int r = i >> 5, c = i & 31;
        float v = Bin[gb0 + (size_t)r * 128 + cg * 32 + c];
        Ssm[r * 33 + c] = v;
        Sst[((size_t)(bh * 15 + 0) * 4 + cg) * 4096 + i] = v;
    }
    __syncthreads();

    for (int ck = 1; ck < NCHUNK - 1; ck++) {
        const size_t gb = gb0 + (size_t)ck * 16384;
        for (int i = t; i < 16384; i += 256) {
            int r = i >> 7, k = i & 127;
            Tg[k * 130 + r] = Gin[gb + i];
        }
        __syncthreads();
        unsigned long long acc[4][2];
#pragma unroll
        for (int i = 0; i < 4; i++) { acc[i][0] = 0ull; acc[i][1] = 0ull; }
        for (int k = 0; k < 128; k++) {
            const unsigned long long* gp =
                (const unsigned long long*)&Tg[k * 130 + tr * 8];
            float sa = Ssm[k * 33 + c0], sb = Ssm[k * 33 + c0 + 1];
            unsigned long long s02 = pk2(sa, sa), s12 = pk2(sb, sb);
#pragma unroll
            for (int i = 0; i < 4; i++) {
                unsigned long long gv = gp[i];
                acc[i][0] = fma2(gv, s02, acc[i][0]);
                acc[i][1] = fma2(gv, s12, acc[i][1]);
            }
        }
        __syncthreads();
        float* sp = Sst + ((size_t)(bh * 15 + ck) * 4 + cg) * 4096;
#pragma unroll
        for (int i = 0; i < 4; i++) {
            int r0 = tr * 8 + 2 * i;
            float x0, x1, y0, y1;
            up2(acc[i][0], x0, x1);
            up2(acc[i][1], y0, y1);
            float v00 = x0 + Bin[gb + (size_t)r0 * 128 + cg * 32 + c0];
            float v01 = y0 + Bin[gb + (size_t)r0 * 128 + cg * 32 + c0 + 1];
            float v10 = x1 + Bin[gb + (size_t)(r0 + 1) * 128 + cg * 32 + c0];
            float v11 = y1 + Bin[gb + (size_t)(r0 + 1) * 128 + cg * 32 + c0 + 1];
            Ssm[r0 * 33 + c0]           = v00;
            Ssm[r0 * 33 + c0 + 1]       = v01;
            Ssm[(r0 + 1) * 33 + c0]     = v10;
            Ssm[(r0 + 1) * 33 + c0 + 1] = v11;
            sp[r0 * 32 + c0]           = v00;
            sp[r0 * 32 + c0 + 1]       = v01;
            sp[(r0 + 1) * 32 + c0]     = v10;
            sp[(r0 + 1) * 32 + c0 + 1] = v11;
        }
        __syncthreads();
    }
}

// ---------------------------------------------------------------------------
// Stitch B: parallel apply. Grid (15, 4 cg, 32 bh), 256 thr.
// ---------------------------------------------------------------------------
__global__ void __launch_bounds__(256)
stitch_apply_kernel(const float* __restrict__ qt, const float* __restrict__ Sst,
                    float* __restrict__ omid)
{
    extern __shared__ float sm[];
    float* Ssm = sm;
    float* Tq  = sm + 128 * 33;
    const int ck = blockIdx.x + 1;
    const int cg = blockIdx.y, bh = blockIdx.z;
    const int b = bh >> 4, h = bh & 15;
    const int t = threadIdx.x;
    const int tc = t & 15, tr = t >> 4;
    const int c0 = 2 * tc;

    const float* sp = Sst + ((size_t)(bh * 15 + ck - 1) * 4 + cg) * 4096;
    for (int i = t; i < 4096; i += 256) {
        int r = i >> 5, c = i & 31;
        Ssm[r * 33 + c] = sp[i];
    }
    const size_t qtb = (size_t)bh * 2048 * 128;
    for (int i = t; i < 16384; i += 256) {
        int tt = i >> 7, k = i & 127;
        Tq[k * 130 + tt] = qt[qtb + (size_t)(ck * 128 + tt) * 128 + k];
    }
    __syncthreads();

    unsigned long long acc[4][2];
#pragma unroll
    for (int i = 0; i < 4; i++) { acc[i][0] = 0ull; acc[i][1] = 0ull; }
    for (int k = 0; k < 128; k++) {
        const unsigned long long* tp =
            (const unsigned long long*)&Tq[k * 130 + tr * 8];
        float sa = Ssm[k * 33 + c0], sb = Ssm[k * 33 + c0 + 1];
        unsigned long long s02 = pk2(sa, sa), s12 = pk2(sb, sb);
#pragma unroll
        for (int i = 0; i < 4; i++) {
            unsigned long long qv = tp[i];
            acc[i][0] = fma2(qv, s02, acc[i][0]);
            acc[i][1] = fma2(qv, s12, acc[i][1]);
        }
    }
#pragma unroll
    for (int i = 0; i < 4; i++) {
        float x0, x1, y0, y1;
        up2(acc[i][0], x0, x1);
        up2(acc[i][1], y0, y1);
        int tt0 = tr * 8 + 2 * i;
        size_t r0 = ((size_t)(b * 2048 + ck * 128 + tt0)) * HID
                    + h * 128 + cg * 32 + c0;
        omid[r0]           += x0;
        omid[r0 + 1]       += y0;
        omid[r0 + HID]     += x1;
        omid[r0 + HID + 1] += y1;
    }
}

// ---------------------------------------------------------------------------
__global__ void __launch_bounds__(256)
gate_norm_kernel(float* __restrict__ o, const float* __restrict__ g,
                 const float* __restrict__ onw)
{
    const int gw = blockIdx.x * 8 + (threadIdx.x >> 5);
    const int lane = threadIdx.x & 31;
    const size_t base = (size_t)gw * 128 + lane * 4;

    float4 ov = *(float4*)&o[base];
    float ss = ov.x * ov.x + ov.y * ov.y + ov.z * ov.z + ov.w * ov.w;
#pragma unroll
    for (int m = 16; m; m >>= 1) ss += __shfl_xor_sync(0xffffffffu, ss, m);
    const float r = rsqrtf(ss * (1.f / 128.f) + 1e-5f);

    float4 gv = *(const float4*)&g[base];
    float4 wv = *(const float4*)&onw[lane * 4];
    float4 res;
    res.x = ov.x * r * wv.x * (gv.x / (1.f + expf(-gv.x)));
    res.y = ov.y * r * wv.y * (gv.y / (1.f + expf(-gv.y)));
    res.z = ov.z * r * wv.z * (gv.z / (1.f + expf(-gv.z)));
    res.w = ov.w * r * wv.w * (gv.w / (1.f + expf(-gv.w)));
    *(float4*)&o[base] = res;
}

// ---------------------------------------------------------------------------
extern "C" void kernel_launch(void* const* d_in, const int* in_sizes, int n_in,
                              void* d_out, int out_size)
{
    const float* x    = (const float*)d_in[0];
    const float* qkvw = (const float*)d_in[1];
    const float* gw   = (const float*)d_in[2];
    const float* bw   = (const float*)d_in[3];
    const float* gkw  = (const float*)d_in[4];
    const float* cw   = (const float*)d_in[5];
    const float* onw  = (const float*)d_in[6];
    const float* ow   = (const float*)d_in[7];
    float* out = (float*)d_out;

    float *qkvb, *convb, *gbuf, *omid, *al, *be, *qtb, *Gb, *Bb, *Sstb;
    __nv_bfloat16 *a3x, *a3o, *b3a, *b3o;
    cudaGetSymbolAddress((void**)&qkvb,  g_qkv);
    cudaGetSymbolAddress((void**)&convb, g_conv);
    cudaGetSymbolAddress((void**)&gbuf,  g_gbuf);
    cudaGetSymbolAddress((void**)&omid,  g_omid);
    cudaGetSymbolAddress((void**)&al,    g_alpha);
    cudaGetSymbolAddress((void**)&be,    g_beta);
    cudaGetSymbolAddress((void**)&qtb,   g_qt);
    cudaGetSymbolAddress((void**)&Gb,    g_G);
    cudaGetSymbolAddress((void**)&Bb,    g_B);
    cudaGetSymbolAddress((void**)&Sstb,  g_Sst);
    cudaGetSymbolAddress((void**)&a3x,   g_a3x);
    cudaGetSymbolAddress((void**)&a3o,   g_a3o);
    cudaGetSymbolAddress((void**)&b3a,   g_b3a);
    cudaGetSymbolAddress((void**)&b3o,   g_b3o);

    cudaFuncSetAttribute(gemm_main,
                         cudaFuncAttributeMaxDynamicSharedMemorySize, GEMM_SMEM);
    cudaFuncSetAttribute(stitch_chain_kernel,
                         cudaFuncAttributeMaxDynamicSharedMemorySize, CHAIN_SMEM);
    cudaFuncSetAttribute(stitch_apply_kernel,
                         cudaFuncAttributeMaxDynamicSharedMemorySize, CHAIN_SMEM);

    // conversions (x + 3 weights, one launch)
    convert_all<<<((BS_TOTAL + QKVD + 2 * HID) * 512 + 255) / 256, 256>>>(
        x, a3x, qkvw, b3a, gw, b3a + (size_t)QKVD * KSPLIT, ow, b3o);
    // fused qkv+g GEMM
    gemm_main<<<dim3(NFUSED / BN, BS_TOTAL / BM), 256, GEMM_SMEM>>>(
        a3x, b3a, x, qkvw, qkvb, gbuf, BS_TOTAL, NFUSED, KSPLIT, HID, QKVD);
    // alpha/beta + conv (separate, static-smem kernels)
    proj_ab_kernel<<<BS_TOTAL / 4, 256>>>(x, gkw, bw, al, be);
    conv_norm_kernel<<<BS_TOTAL, 256>>>(qkvb, cw, convb);
    // recurrence (256-thread, reg-cached)
    recur_chunk_kernel<<<dim3(4, NCHUNK, 32), 256>>>(convb, al, be, omid,
                                                     qtb, Gb, Bb);
    // stitch
    stitch_chain_kernel<<<dim3(4, 32), 256, CHAIN_SMEM>>>(Gb, Bb, Sstb);
    stitch_apply_kernel<<<dim3(15, 4, 32), 256, CHAIN_SMEM>>>(qtb, Sstb, omid);
    // gated RMSNorm + output path
    gate_norm_kernel<<<BS_TOTAL * NH / 8, 256>>>(omid, gbuf, onw);
    convert_split<<<(BS_TOTAL * 512 + 255) / 256, 256>>>(omid, a3o, BS_TOTAL * 512, 0);
    gemm_main<<<dim3(HID / BN, BS_TOTAL / BM), 256, GEMM_SMEM>>>(
        a3o, b3o, omid, ow, out, out, BS_TOTAL, HID, KSPLIT, HID, HID);
}

// round 16
// speedup vs baseline: 1.1048x; 1.1048x over previous
#include <cuda_runtime.h>
#include <cuda_bf16.h>
#include <math.h>
#include <stdint.h>

// ---------------------------------------------------------------------------
// GatedDeltaNet forward. tcgen05 bf16-split GEMMs (BM=256, 3-stage cp.async,
// fused qkv+g launch), chunked delta-rule recurrence (128-thread 4-loop,
// padded conflict-free smem, dead-work pruning), split stitch.
// B=2, S=2048, HID=2048, H=16, HKV=4, DK=DV=128.
// ---------------------------------------------------------------------------

#if defined(__CUDA_ARCH__) && !defined(__CUDA_ARCH_FEAT_SM103_ALL)
#define NO_TCGEN05 1
#endif

#define BS_TOTAL 4096
#define HID 2048
#define QKVD 3072
#define NH 16
#define KSPLIT 6144
#define NCHUNK 16
#define CLEN 128
#define NFUSED 5120          // QKVD + HID

// ---------------- scratch (device globals; no runtime allocation) ----------
__device__ float g_qkv [ (size_t)BS_TOTAL * QKVD ];
__device__ float g_conv[ (size_t)BS_TOTAL * QKVD ];
__device__ float g_gbuf[ (size_t)BS_TOTAL * HID  ];
__device__ float g_omid[ (size_t)BS_TOTAL * HID  ];
__device__ float g_alpha[ BS_TOTAL * NH ];
__device__ float g_beta [ BS_TOTAL * NH ];
__device__ float g_qt  [ (size_t)32 * 2048 * 128 ];
__device__ float g_G   [ (size_t)32 * NCHUNK * 128 * 128 ];
__device__ float g_B   [ (size_t)32 * NCHUNK * 128 * 128 ];
__device__ float g_Sst [ (size_t)32 * 15 * 4 * 4096 ];
__device__ __nv_bfloat16 g_a3x [ (size_t)BS_TOTAL * KSPLIT ];
__device__ __nv_bfloat16 g_a3o [ (size_t)BS_TOTAL * KSPLIT ];
__device__ __nv_bfloat16 g_b3a [ (size_t)NFUSED   * KSPLIT ];
__device__ __nv_bfloat16 g_b3o [ (size_t)HID      * KSPLIT ];

// ---------------- f32x2 packed helpers -------------------------------------
__device__ __forceinline__ unsigned long long pk2(float lo, float hi) {
    unsigned long long r;
    asm("mov.b64 %0, {%1, %2};" : "=l"(r)
        : "r"(__float_as_uint(lo)), "r"(__float_as_uint(hi)));
    return r;
}
__device__ __forceinline__ void up2(unsigned long long v, float& lo, float& hi) {
    unsigned int a, b;
    asm("mov.b64 {%0, %1}, %2;" : "=r"(a), "=r"(b) : "l"(v));
    lo = __uint_as_float(a); hi = __uint_as_float(b);
}
__device__ __forceinline__ unsigned long long fma2(unsigned long long a,
                                                   unsigned long long b,
                                                   unsigned long long c) {
    unsigned long long d;
    asm("fma.rn.f32x2 %0, %1, %2, %3;" : "=l"(d) : "l"(a), "l"(b), "l"(c));
    return d;
}
__device__ __forceinline__ unsigned long long mul2(unsigned long long a,
                                                   unsigned long long b) {
    unsigned long long d;
    asm("mul.rn.f32x2 %0, %1, %2;" : "=l"(d) : "l"(a), "l"(b));
    return d;
}

// ---------------- common helpers -------------------------------------------
__device__ __forceinline__ uint32_t smem_u32(const void* p) {
    uint32_t a;
    asm("{ .reg .u64 t; cvta.to.shared.u64 t, %1; cvt.u32.u64 %0, t; }"
        : "=r"(a) : "l"(p));
    return a;
}

#define SW128(o) ((o) ^ (((o) >> 3) & 0x70))

#define CP_ASYNC16(sa, g) \
    asm volatile("cp.async.cg.shared.global [%0], [%1], 16;" \
                 :: "r"(sa), "l"(g) : "memory")
#define CP_COMMIT() asm volatile("cp.async.commit_group;" ::: "memory")
#define CP_WAIT(n)  asm volatile("cp.async.wait_group %0;" :: "n"(n) : "memory")

#ifndef NO_TCGEN05
__device__ __forceinline__ bool elect1() {
    uint32_t p;
    asm volatile("{ .reg .pred p; elect.sync _|p, 0xFFFFFFFF; selp.b32 %0,1,0,p; }"
                 : "=r"(p));
    return p != 0;
}
#define MBAR_INIT(a, c) \
    asm volatile("mbarrier.init.shared.b64 [%0], %1;" :: "r"(a), "r"(c) : "memory")
#define MBAR_WAIT(a, ph) do {                                                   \
    uint32_t _m = (a); uint32_t _p = (ph); uint32_t _d;                         \
    asm volatile("{\n\t.reg .pred p;\n\t"                                       \
        "mbarrier.try_wait.parity.acquire.cta.shared::cta.b64 p, [%1], %2;\n\t" \
        "selp.b32 %0, 1, 0, p;\n\t}"                                            \
        : "=r"(_d) : "r"(_m), "r"(_p) : "memory");                              \
    if (!_d) {                                                                  \
        asm volatile("{\n\t.reg .pred P1;\n\t"                                  \
            "WL_%=:\n\t"                                                        \
            "mbarrier.try_wait.parity.acquire.cta.shared::cta.b64 P1, [%0], %1, 0x989680;\n\t" \
            "@P1 bra.uni WD_%=;\n\t"                                            \
            "bra.uni WL_%=;\n\t"                                                \
            "WD_%=:\n\t}"                                                       \
            :: "r"(_m), "r"(_p) : "memory");                                    \
    }                                                                           \
} while (0)

#define TM_ALLOC(sa, n) \
    asm volatile("tcgen05.alloc.cta_group::1.sync.aligned.shared::cta.b32 [%0], %1;" \
                 :: "r"(sa), "r"(n) : "memory")
#define TM_DEALLOC(t, n) \
    asm volatile("tcgen05.dealloc.cta_group::1.sync.aligned.b32 %0, %1;" :: "r"(t), "r"(n))
#define TM_COMMIT(mb) \
    asm volatile("tcgen05.commit.cta_group::1.mbarrier::arrive::one.shared::cluster.b64 [%0];" \
                 :: "r"(mb) : "memory")
#define FENCE_ASYNC() asm volatile("fence.proxy.async.shared::cta;" ::: "memory")
#define TM_FENCE_AFTER() asm volatile("tcgen05.fence::after_thread_sync;" ::: "memory")
#define TM_WAIT_LD() asm volatile("tcgen05.wait::ld.sync.aligned;" ::: "memory")

__device__ __forceinline__ void mma_f16_ss(uint32_t d, uint64_t ad, uint64_t bd,
                                           uint32_t idesc, bool acc) {
    uint32_t en = acc ? 1u : 0u, z = 0u;
    asm volatile("{\n\t.reg .pred p;\n\tsetp.ne.u32 p, %5, 0;\n\t"
        "tcgen05.mma.cta_group::1.kind::f16 [%0], %1, %2, %3, {%4, %4, %4, %4}, p;\n\t}"
        :: "r"(d), "l"(ad), "l"(bd), "r"(idesc), "r"(z), "r"(en) : "memory");
}

#define LDTM_X32(r, a) \
    asm volatile("tcgen05.ld.sync.aligned.32x32b.x32.b32 "                      \
        "{%0, %1, %2, %3, %4, %5, %6, %7, "                                     \
        " %8, %9, %10, %11, %12, %13, %14, %15, "                               \
        " %16, %17, %18, %19, %20, %21, %22, %23, "                             \
        " %24, %25, %26, %27, %28, %29, %30, %31}, [%32];"                      \
        : "=r"((r)[0]),  "=r"((r)[1]),  "=r"((r)[2]),  "=r"((r)[3]),            \
          "=r"((r)[4]),  "=r"((r)[5]),  "=r"((r)[6]),  "=r"((r)[7]),            \
          "=r"((r)[8]),  "=r"((r)[9]),  "=r"((r)[10]), "=r"((r)[11]),           \
          "=r"((r)[12]), "=r"((r)[13]), "=r"((r)[14]), "=r"((r)[15]),           \
          "=r"((r)[16]), "=r"((r)[17]), "=r"((r)[18]), "=r"((r)[19]),           \
          "=r"((r)[20]), "=r"((r)[21]), "=r"((r)[22]), "=r"((r)[23]),           \
          "=r"((r)[24]), "=r"((r)[25]), "=r"((r)[26]), "=r"((r)[27]),           \
          "=r"((r)[28]), "=r"((r)[29]), "=r"((r)[30]), "=r"((r)[31])            \
        : "r"(a))
#endif // !NO_TCGEN05

// ---------------------------------------------------------------------------
// Split conversion helper.
// ---------------------------------------------------------------------------
__device__ __forceinline__ void split_row4(const float* in, __nv_bfloat16* out,
                                           int idx, int mode)
{
    int r = idx >> 9, c4 = idx & 511;
    float4 v = ((const float4*)in)[idx];
    __nv_bfloat16 h0 = __float2bfloat16_rn(v.x);
    __nv_bfloat16 h1 = __float2bfloat16_rn(v.y);
    __nv_bfloat16 h2 = __float2bfloat16_rn(v.z);
    __nv_bfloat16 h3 = __float2bfloat16_rn(v.w);
    __nv_bfloat16 l0 = __float2bfloat16_rn(v.x - __bfloat162float(h0));
    __nv_bfloat16 l1 = __float2bfloat16_rn(v.y - __bfloat162float(h1));
    __nv_bfloat16 l2 = __float2bfloat16_rn(v.z - __bfloat162float(h2));
    __nv_bfloat16 l3 = __float2bfloat16_rn(v.w - __bfloat162float(h3));
    uint2 hv, lv;
    hv.x = (uint32_t)__bfloat16_as_ushort(h0) | ((uint32_t)__bfloat16_as_ushort(h1) << 16);
    hv.y = (uint32_t)__bfloat16_as_ushort(h2) | ((uint32_t)__bfloat16_as_ushort(h3) << 16);
    lv.x = (uint32_t)__bfloat16_as_ushort(l0) | ((uint32_t)__bfloat16_as_ushort(l1) << 16);
    lv.y = (uint32_t)__bfloat16_as_ushort(l2) | ((uint32_t)__bfloat16_as_ushort(l3) << 16);
    size_t base = (size_t)r * KSPLIT + c4 * 4;
    *(uint2*)&out[base] = hv;
    if (mode == 0) {
        *(uint2*)&out[base + 2048] = hv;
        *(uint2*)&out[base + 4096] = lv;
    } else {
        *(uint2*)&out[base + 2048] = lv;
        *(uint2*)&out[base + 4096] = hv;
    }
}

__global__ void __launch_bounds__(256)
convert_all(const float* __restrict__ x, __nv_bfloat16* __restrict__ ax,
            const float* __restrict__ qkvw, __nv_bfloat16* __restrict__ bq,
            const float* __restrict__ gw, __nv_bfloat16* __restrict__ bg,
            const float* __restrict__ ow, __nv_bfloat16* __restrict__ bo)
{
    int idx = blockIdx.x * 256 + threadIdx.x;
    if (idx < BS_TOTAL * 512) {
        split_row4(x, ax, idx, 0);
        return;
    }
    idx -= BS_TOTAL * 512;
    if (idx < QKVD * 512)
        split_row4(qkvw, bq, idx, 1);
    else if (idx < (QKVD + HID) * 512)
        split_row4(gw, bg, idx - QKVD * 512, 1);
    else if (idx < (QKVD + 2 * HID) * 512)
        split_row4(ow, bo, idx - (QKVD + HID) * 512, 1);
}

__global__ void __launch_bounds__(256)
convert_split(const float* __restrict__ in, __nv_bfloat16* __restrict__ out,
              int total4, int mode)
{
    int idx = blockIdx.x * 256 + threadIdx.x;
    if (idx < total4) split_row4(in, out, idx, mode);
}

// ---------------------------------------------------------------------------
// Main GEMM: BM=256, BN=256, BK=64, 3-stage cp.async, 1 CTA/SM.
// ---------------------------------------------------------------------------
#define BM 256
#define BN 256
#define BK 64
#define NSTAGE 3
#define STAGE_BYTES 65536
#define GEMM_SMEM (1024 + NSTAGE*STAGE_BYTES)

__global__ void __launch_bounds__(256, 1) __cluster_dims__(1, 1, 1)
gemm_main(const __nv_bfloat16* __restrict__ A3, const __nv_bfloat16* __restrict__ B3,
          const float* __restrict__ Af, const float* __restrict__ Bf,
          float* __restrict__ C, float* __restrict__ C2,
          int M, int N, int K3, int Kf, int Nsplit)
{
    extern __shared__ char smem[];
#ifndef NO_TCGEN05
    const uint32_t sbase = smem_u32(smem);
    const int tid = threadIdx.x;
    const int wid = tid >> 5, lane = tid & 31;
    const int bm = blockIdx.y * BM, bn = blockIdx.x * BN;

    const uint32_t IDESC =
        (1u << 4) | (1u << 7) | (1u << 10) | ((BN / 8) << 17) | ((128 / 16) << 24);
    const unsigned long long DESC_BASE =
        (2ull << 61) | (1ull << 46) | (64ull << 32) | (1ull << 16);

    if (wid == 0) TM_ALLOC(sbase + 0, 512);
    if (tid == 0) {
        MBAR_INIT(sbase + 8, 1);  MBAR_INIT(sbase + 16, 1);
        MBAR_INIT(sbase + 24, 1);
    }
    __syncthreads();
    uint32_t tmem;
    asm volatile("ld.shared.b32 %0, [%1];" : "=r"(tmem) : "r"(sbase + 0));

    const int NK = K3 / BK;
    const __nv_bfloat16* Ab = A3 + (size_t)bm * K3;
    const __nv_bfloat16* Bb = B3 + (size_t)bn * K3;

    auto load_stage = [&](int kt, int s) {
        const uint32_t sa = sbase + 1024 + s * STAGE_BYTES;
        const __nv_bfloat16* Ak = Ab + (size_t)kt * BK;
#pragma unroll
        for (int i = 0; i < 8; i++) {
            int chunk = tid + 256 * i;
            int row = chunk >> 3, c = chunk & 7;
            CP_ASYNC16(sa + SW128(row * 128 + c * 16),
                       Ak + (size_t)row * K3 + c * 8);
        }
        const __nv_bfloat16* Bk = Bb + (size_t)kt * BK;
        const uint32_t sb = sa + 32768;
#pragma unroll
        for (int i = 0; i < 8; i++) {
            int chunk = tid + 256 * i;
            int row = chunk >> 3, c = chunk & 7;
            CP_ASYNC16(sb + SW128(row * 128 + c * 16),
                       Bk + (size_t)row * K3 + c * 8);
        }
    };

    load_stage(0, 0); CP_COMMIT();
    load_stage(1, 1); CP_COMMIT();

    int ph[NSTAGE] = {0, 0, 0};
    int sidx = 0;
    for (int kt = 0; kt < NK; kt++) {
        const int s = sidx;
        CP_WAIT(1);
        __syncthreads();
        if (wid == 0) {
            FENCE_ASYNC();
            if (elect1()) {
                const uint32_t st = sbase + 1024 + s * STAGE_BYTES;
                uint64_t ad = DESC_BASE | ((st >> 4) & 0x3FFF);
                uint64_t bd = DESC_BASE | (((st + 32768) >> 4) & 0x3FFF);
#pragma unroll
                for (int half = 0; half < 2; half++)
#pragma unroll
                    for (int kc = 0; kc < 4; kc++)
                        mma_f16_ss(tmem + half * 256,
                                   ad + half * 1024 + kc * 2, bd + kc * 2,
                                   IDESC, (kt > 0) || (kc > 0));
                TM_COMMIT(sbase + 8 + s * 8);
            }
        }
        const int kn = kt + 2;
        if (kn < NK) {
            int sp = s + 2; if (sp >= NSTAGE) sp -= NSTAGE;
            if (kt >= 1) {
                MBAR_WAIT(sbase + 8 + sp * 8, ph[sp]);
                ph[sp] ^= 1;
            }
            load_stage(kn, sp);
            CP_COMMIT();
        }
        sidx = s + 1; if (sidx >= NSTAGE) sidx -= NSTAGE;
    }
    {
        int sl = (NK - 1) % NSTAGE;
        MBAR_WAIT(sbase + 8 + sl * 8, ph[sl]);
    }
    TM_FENCE_AFTER();

    {
        const int sub = wid & 3, half = wid >> 2;
        const int gc0 = bn + half * 128;
        float* base; int ld, coff;
        if (gc0 < Nsplit) { base = C;  ld = Nsplit;     coff = gc0; }
        else              { base = C2; ld = N - Nsplit; coff = gc0 - Nsplit; }
#pragma unroll
        for (int mh = 0; mh < 2; mh++) {
            const int row = bm + mh * 128 + sub * 32 + lane;
            float* crow = base + (size_t)row * ld + coff;
#pragma unroll
            for (int cb = 0; cb < 4; cb++) {
                uint32_t r[32];
                LDTM_X32(r, tmem + mh * 256 + half * 128 + cb * 32);
                TM_WAIT_LD();
#pragma unroll
                for (int j = 0; j < 8; j++) {
                    float4 o = make_float4(__uint_as_float(r[4 * j + 0]),
                                           __uint_as_float(r[4 * j + 1]),
                                           __uint_as_float(r[4 * j + 2]),
                                           __uint_as_float(r[4 * j + 3]));
                    *(float4*)(crow + cb * 32 + 4 * j) = o;
                }
            }
        }
    }
    __syncthreads();
    if (wid == 0) TM_DEALLOC(tmem, 512);

#else  // ---------------- fp32 f32x2 fallback (non-'a' pass) ----------------
    float* As = (float*)smem;
    float* Bs = As + 2 * 16 * 132;
    const int tid = threadIdx.x;
    const int tx = tid & 15, ty = tid >> 4;
    const int lr = tid >> 2, lk = (tid & 3) * 4;
    const int K = Kf;
    const size_t rowK64 = (size_t)64 * K;

    for (int sub = 0; sub < 4; sub++) {
        const int bm = blockIdx.y * BM + (sub >> 1) * 128;
        const int bn = blockIdx.x * BN + (sub & 1) * 128;
        const float* Aptr = Af + (size_t)(bm + lr) * K + lk;
        const float* Bptr = Bf + (size_t)(bn + lr) * K + lk;
        float* cbase; int ld, coff;
        if (bn < Nsplit) { cbase = C;  ld = Nsplit;     coff = bn; }
        else             { cbase = C2; ld = N - Nsplit; coff = bn - Nsplit; }

        unsigned long long acc[8][4];
#pragma unroll
        for (int i = 0; i < 8; i++)
#pragma unroll
            for (int j = 0; j < 4; j++) acc[i][j] = 0ull;

        float4 a0 = *(const float4*)(Aptr);
        float4 a1 = *(const float4*)(Aptr + rowK64);
        float4 b0 = *(const float4*)(Bptr);
        float4 b1 = *(const float4*)(Bptr + rowK64);
        int buf = 0;
#define AS(b,k,i) As[((b)*16 + (k)) * 132 + (i)]
#define BS(b,k,i) Bs[((b)*16 + (k)) * 132 + (i)]
        AS(buf,lk+0,lr)=a0.x; AS(buf,lk+1,lr)=a0.y; AS(buf,lk+2,lr)=a0.z; AS(buf,lk+3,lr)=a0.w;
        AS(buf,lk+0,lr+64)=a1.x; AS(buf,lk+1,lr+64)=a1.y; AS(buf,lk+2,lr+64)=a1.z; AS(buf,lk+3,lr+64)=a1.w;
        BS(buf,lk+0,lr)=b0.x; BS(buf,lk+1,lr)=b0.y; BS(buf,lk+2,lr)=b0.z; BS(buf,lk+3,lr)=b0.w;
        BS(buf,lk+0,lr+64)=b1.x; BS(buf,lk+1,lr+64)=b1.y; BS(buf,lk+2,lr+64)=b1.z; BS(buf,lk+3,lr+64)=b1.w;
        __syncthreads();

        const int nk = K >> 4;
        for (int kt = 0; kt < nk; kt++) {
            const bool hasNext = (kt + 1) < nk;
            float4 na0, na1, nb0, nb1;
            if (hasNext) {
                const float* Ap = Aptr + (size_t)(kt + 1) * 16;
                const float* Bp = Bptr + (size_t)(kt + 1) * 16;
                na0 = *(const float4*)(Ap);  na1 = *(const float4*)(Ap + rowK64);
                nb0 = *(const float4*)(Bp);  nb1 = *(const float4*)(Bp + rowK64);
            }
#pragma unroll
            for (int kk = 0; kk < 16; kk++) {
                float4 af0 = *(const float4*)&AS(buf, kk, ty * 8);
                float4 af1 = *(const float4*)&AS(buf, kk, ty * 8 + 4);
                ulonglong2 bp0 = *(const ulonglong2*)&BS(buf, kk, tx * 8);
                ulonglong2 bp1 = *(const ulonglong2*)&BS(buf, kk, tx * 8 + 4);
                unsigned long long bb[4] = { bp0.x, bp0.y, bp1.x, bp1.y };
                unsigned long long a2[8];
                a2[0]=pk2(af0.x,af0.x); a2[1]=pk2(af0.y,af0.y);
                a2[2]=pk2(af0.z,af0.z); a2[3]=pk2(af0.w,af0.w);
                a2[4]=pk2(af1.x,af1.x); a2[5]=pk2(af1.y,af1.y);
                a2[6]=pk2(af1.z,af1.z); a2[7]=pk2(af1.w,af1.w);
#pragma unroll
                for (int i = 0; i < 8; i++) {
                    acc[i][0] = fma2(a2[i], bb[0], acc[i][0]);
                    acc[i][1] = fma2(a2[i], bb[1], acc[i][1]);
                    acc[i][2] = fma2(a2[i], bb[2], acc[i][2]);
                    acc[i][3] = fma2(a2[i], bb[3], acc[i][3]);
                }
            }
            if (hasNext) {
                buf ^= 1;
                __syncthreads();
                AS(buf,lk+0,lr)=na0.x; AS(buf,lk+1,lr)=na0.y; AS(buf,lk+2,lr)=na0.z; AS(buf,lk+3,lr)=na0.w;
                AS(buf,lk+0,lr+64)=na1.x; AS(buf,lk+1,lr+64)=na1.y; AS(buf,lk+2,lr+64)=na1.z; AS(buf,lk+3,lr+64)=na1.w;
                BS(buf,lk+0,lr)=nb0.x; BS(buf,lk+1,lr)=nb0.y; BS(buf,lk+2,lr)=nb0.z; BS(buf,lk+3,lr)=nb0.w;
                BS(buf,lk+0,lr+64)=nb1.x; BS(buf,lk+1,lr+64)=nb1.y; BS(buf,lk+2,lr+64)=nb1.z; BS(buf,lk+3,lr+64)=nb1.w;
                __syncthreads();
            }
        }
#undef AS
#undef BS
#pragma unroll
        for (int i = 0; i < 8; i++) {
            float r0,r1,r2,r3,r4,r5,r6,r7;
            up2(acc[i][0],r0,r1); up2(acc[i][1],r2,r3);
            up2(acc[i][2],r4,r5); up2(acc[i][3],r6,r7);
            float* cp = cbase + (size_t)(bm + ty * 8 + i) * ld + coff + tx * 8;
            *(float4*)(cp)     = make_float4(r0,r1,r2,r3);
            *(float4*)(cp + 4) = make_float4(r4,r5,r6,r7);
        }
        __syncthreads();
    }
#endif
}

// ---------------------------------------------------------------------------
// Causal depthwise conv (K=4) + SiLU + per-head l2norm (static smem).
// ---------------------------------------------------------------------------
__global__ void __launch_bounds__(256)
conv_norm_kernel(const float* __restrict__ qkv, const float* __restrict__ cw,
                 float* __restrict__ out)
{
    const int bs = blockIdx.x;
    const int b = bs >> 11, s = bs & 2047;
    __shared__ float buf[QKVD];
    __shared__ float sc[20];
    const size_t rowbase = (size_t)bs * QKVD;

    for (int c = threadIdx.x; c < QKVD; c += 256) {
        float acc = 0.f;
#pragma unroll
        for (int i = 0; i < 4; i++) {
            int sp = s - 3 + i;
            if (sp >= 0)
                acc += cw[c * 4 + i] * qkv[((size_t)(b * 2048 + sp)) * QKVD + c];
        }
        buf[c] = acc / (1.f + expf(-acc));
    }
    __syncthreads();

    const int w = threadIdx.x >> 5, lane = threadIdx.x & 31;
    for (int hd = w; hd < 20; hd += 8) {
        const int base = (hd < 16) ? hd * 128 : 2048 + (hd - 16) * 128;
        float ss = 0.f;
#pragma unroll
        for (int j = 0; j < 4; j++) {
            float x = buf[base + lane + 32 * j];
            ss += x * x;
        }
#pragma unroll
        for (int m = 16; m; m >>= 1) ss += __shfl_xor_sync(0xffffffffu, ss, m);
        if (lane == 0) {
            float r = rsqrtf(ss + 1e-6f);
            sc[hd] = (hd < 16) ? r * 0.08838834764831845f : r;
        }
    }
    __syncthreads();

    for (int c = threadIdx.x; c < QKVD; c += 256) {
        float scale = (c < 2048) ? sc[c >> 7]
                    : (c < 2560) ? sc[16 + ((c - 2048) >> 7)]
                                 : 1.f;
        out[rowbase + c] = buf[c] * scale;
    }
}

// ---------------------------------------------------------------------------
// alpha/beta projections, 4 bs-rows per block (static smem).
// ---------------------------------------------------------------------------
__global__ void __launch_bounds__(256)
proj_ab_kernel(const float* __restrict__ x, const float* __restrict__ gkw,
               const float* __restrict__ bw, float* __restrict__ alpha,
               float* __restrict__ beta)
{
    const int bs0 = blockIdx.x * 4;
    __shared__ __align__(16) float xs[4][HID];
    for (int i = threadIdx.x * 4; i < 4 * HID; i += 256 * 4) {
        int r = i >> 11, c = i & (HID - 1);
        *(float4*)&xs[r][c] = *(const float4*)&x[(size_t)(bs0 + r) * HID + c];
    }
    __syncthreads();

    const int w = threadIdx.x >> 5, lane = threadIdx.x & 31;
    for (int out = w; out < 32; out += 8) {
        const float* wr = (out < 16) ? gkw + (size_t)out * HID
                                     : bw + (size_t)(out - 16) * HID;
        const float4* w4 = (const float4*)wr;
        float acc0 = 0.f, acc1 = 0.f, acc2 = 0.f, acc3 = 0.f;
#pragma unroll 4
        for (int j = 0; j < 16; j++) {
            float4 q = w4[lane + 32 * j];
            float4 a0 = ((const float4*)xs[0])[lane + 32 * j];
            float4 a1 = ((const float4*)xs[1])[lane + 32 * j];
            float4 a2 = ((const float4*)xs[2])[lane + 32 * j];
            float4 a3 = ((const float4*)xs[3])[lane + 32 * j];
            acc0 += a0.x*q.x + a0.y*q.y + a0.z*q.z + a0.w*q.w;
            acc1 += a1.x*q.x + a1.y*q.y + a1.z*q.z + a1.w*q.w;
            acc2 += a2.x*q.x + a2.y*q.y + a2.z*q.z + a2.w*q.w;
            acc3 += a3.x*q.x + a3.y*q.y + a3.z*q.z + a3.w*q.w;
        }
#pragma unroll
        for (int m = 16; m; m >>= 1) {
            acc0 += __shfl_down_sync(0xffffffffu, acc0, m);
            acc1 += __shfl_down_sync(0xffffffffu, acc1, m);
            acc2 += __shfl_down_sync(0xffffffffu, acc2, m);
            acc3 += __shfl_down_sync(0xffffffffu, acc3, m);
        }
        if (lane == 0) {
            float accs[4] = {acc0, acc1, acc2, acc3};
#pragma unroll
            for (int r = 0; r < 4; r++) {
                float p = accs[r];
                int bs = bs0 + r;
                if (out < 16) {
                    float ls = fminf(p, 0.f) - log1pf(expf(-fabsf(p)));
                    alpha[bs * NH + out] = expf(ls * 0.0625f);
                } else {
                    beta[bs * NH + (out - 16)] = 1.f / (1.f + expf(-p));
                }
            }
        }
    }
}

// ---------------------------------------------------------------------------
// Chunked delta recurrence, phase 1 (128-thread 4-loop form; padded smem).
// Dead-work pruning: ck==0 skips G/qt work; ck==15 skips G/B stores.
// ---------------------------------------------------------------------------
__global__ void __launch_bounds__(128)
recur_chunk_kernel(const float* __restrict__ conv, const float* __restrict__ alpha,
                   const float* __restrict__ beta, float* __restrict__ omid,
                   float* __restrict__ qt, float* __restrict__ Gout,
                   float* __restrict__ Bout)
{
    const int cg = blockIdx.x;
    const int ck = blockIdx.y;
    const int bh = blockIdx.z;
    const int b = bh >> 4, h = bh & 15;
    const int t = threadIdx.x;
    const int cq = t >> 2, rg = t & 3;
    const int col = cg * 32 + cq;
    const int kh = h >> 2;
    const int woff = ((t >> 5) * 34) + (t & 31);
    const bool needG = (ck != 0);

    __shared__ __align__(16) float kqf[4][2][136];

    unsigned long long S2[16], G2[16];
#pragma unroll
    for (int i = 0; i < 16; i++) {
        S2[i] = 0ull;
        int r0 = rg * 32 + 2 * i;
        G2[i] = pk2((r0 == col) ? 1.f : 0.f, (r0 + 1 == col) ? 1.f : 0.f);
    }

    const int s0g = ck * CLEN;
    const size_t bb0 = (size_t)b * 2048 * QKVD;
    const float* qc = conv + bb0 + (size_t)s0g * QKVD + h * 128;
    const float* kc = conv + bb0 + (size_t)s0g * QKVD + 2048 + kh * 128;
    const float* vc = conv + bb0 + (size_t)s0g * QKVD + 2560 + kh * 128 + col;
    const float* abase = alpha + (size_t)(b * 2048 + s0g) * NH + h;
    const float* bbase = beta  + (size_t)(b * 2048 + s0g) * NH + h;
    float* obase  = omid + (size_t)(b * 2048 + s0g) * HID + h * 128;
    float* qtbase = qt + ((size_t)bh * 2048 + s0g) * 128;

    kqf[0][0][woff] = kc[t];
    kqf[0][1][woff] = qc[t];
    float kst = kc[QKVD + t];
    float qst = qc[QKVD + t];
    float vA = vc[0],  vB = vc[QKVD];
    float aA = abase[0], aB = abase[NH];
    float bA = bbase[0], bB = bbase[NH];
    __syncthreads();

    for (int s = 0; s < CLEN; s++) {
        kqf[(s + 1) & 3][0][woff] = kst;
        kqf[(s + 1) & 3][1][woff] = qst;
        const int sn = (s + 2 < CLEN) ? s + 2 : CLEN - 1;
        kst = kc[(size_t)sn * QKVD + t];
        qst = qc[(size_t)sn * QKVD + t];
        float vN = vc[(size_t)sn * QKVD];
        float aN = abase[sn * NH];
        float bN = bbase[sn * NH];
        __syncthreads();

        const unsigned long long* k2 =
            (const unsigned long long*)kqf[s & 3][0] + rg * 17;
        const unsigned long long* q2 =
            (const unsigned long long*)kqf[s & 3][1] + rg * 17;
        const unsigned long long a2 = pk2(aA, aA);

        if (needG) {
            unsigned long long uA = 0ull;
#pragma unroll
            for (int i = 0; i < 16; i++) uA = fma2(k2[i], G2[i], uA);
            float ux, uy; up2(uA, ux, uy);
            float u = ux + uy;
            u += __shfl_xor_sync(0xffffffffu, u, 1);
            u += __shfl_xor_sync(0xffffffffu, u, 2);
            const float w = aA * bA * u;
            const unsigned long long w2 = pk2(-w, -w);
            unsigned long long qacc = 0ull;
#pragma unroll
            for (int i = 0; i < 16; i++) {
                unsigned long long g = mul2(G2[i], a2);
                g = fma2(k2[i], w2, g);
                G2[i] = g;
                qacc = fma2(q2[i], g, qacc);
            }
            float qx, qy; up2(qacc, qx, qy);
            float qtv = qx + qy;
            qtv += __shfl_xor_sync(0xffffffffu, qtv, 1);
            qtv += __shfl_xor_sync(0xffffffffu, qtv, 2);
            if (rg == 0) qtbase[(size_t)s * 128 + col] = qtv;
        }

        unsigned long long vpA = 0ull;
#pragma unroll
        for (int i = 0; i < 16; i++) {
            unsigned long long sv = mul2(S2[i], a2);
            vpA = fma2(k2[i], sv, vpA);
            S2[i] = sv;
        }
        float px, py; up2(vpA, px, py);
        float vp = px + py;
        vp += __shfl_xor_sync(0xffffffffu, vp, 1);
        vp += __shfl_xor_sync(0xffffffffu, vp, 2);
        const float delta = (vA - vp) * bA;
        const unsigned long long d2 = pk2(delta, delta);

        unsigned long long oacc = 0ull;
#pragma unroll
        for (int i = 0; i < 16; i++) {
            unsigned long long sv = fma2(k2[i], d2, S2[i]);
            S2[i] = sv;
            oacc = fma2(q2[i], sv, oacc);
        }
        float ox, oy; up2(oacc, ox, oy);
        float osum = ox + oy;
        osum += __shfl_xor_sync(0xffffffffu, osum, 1);
        osum += __shfl_xor_sync(0xffffffffu, osum, 2);
        if (rg == 0) obase[(size_t)s * HID + col] = osum;

        vA = vB; vB = vN;
        aA = aB; aB = aN;
        bA = bB; bB = bN;
    }

    if (ck <= 14) {
        float* Bp = Bout + ((size_t)bh * NCHUNK + ck) * 16384;
#pragma unroll
        for (int i = 0; i < 16; i++) {
            int r0 = rg * 32 + 2 * i;
            float s0v, s1v; up2(S2[i], s0v, s1v);
            Bp[(size_t)r0 * 128 + col]       = s0v;
            Bp[(size_t)(r0 + 1) * 128 + col] = s1v;
        }
        if (needG) {
            float* Gp = Gout + ((size_t)bh * NCHUNK + ck) * 16384;
#pragma unroll
            for (int i = 0; i < 16; i++) {
                int r0 = rg * 32 + 2 * i;
                float g0, g1; up2(G2[i], g0, g1);
                Gp[(size_t)r0 * 128 + col]       = g0;
                Gp[(size_t)(r0 + 1) * 128 + col] = g1;
            }
        }
    }
}

// ---------------------------------------------------------------------------
// Stitch A: serial S_start chain. Grid (4 cg, 32 bh), 256 thr.
// ---------------------------------------------------------------------------
#define CHAIN_SMEM (128*33*4 + 128*130*4)

__global__ void __launch_bounds__(256)
stitch_chain_kernel(const float* __restrict__ Gin, const float* __restrict__ Bin,
                    float* __restrict__ Sst)
{
    extern __shared__ float sm[];
    float* Ssm = sm;
    float* Tg  = sm + 128 * 33;
    const int cg = blockIdx.x, bh = blockIdx.y;
    const int t = threadIdx.x;
    const int tc = t & 15, tr = t >> 4;
    const int c0 = 2 * tc;
    const size_t gb0 = (size_t)bh * NCHUNK * 16384;

    for (int i = t; i < 4096; i += 256) {
        int r = i >> 5, c = i & 31;
        float v = Bin[gb0 + (size_t)r * 128 + cg * 32 + c];
        Ssm[r * 33 + c] = v;
        Sst[((size_t)(bh * 15 + 0) * 4 + cg) * 4096 + i] = v;
    }
    __syncthreads();

    for (int ck = 1; ck < NCHUNK - 1; ck++) {
        const size_t gb = gb0 + (size_t)ck * 16384;
        for (int i = t; i < 16384; i += 256) {
            int r = i >> 7, k = i & 127;
            Tg[k * 130 + r] = Gin[gb + i];
        }
        __syncthreads();
        unsigned long long acc[4][2];
#pragma unroll
        for (int i = 0; i < 4; i++) { acc[i][0] = 0ull; acc[i][1] = 0ull; }
        for (int k = 0; k < 128; k++) {
            const unsigned long long* gp =
                (const unsigned long long*)&Tg[k * 130 + tr * 8];
            float sa = Ssm[k * 33 + c0], sb = Ssm[k * 33 + c0 + 1];
            unsigned long long s02 = pk2(sa, sa), s12 = pk2(sb, sb);
#pragma unroll
            for (int i = 0; i < 4; i++) {
                unsigned long long gv = gp[i];
                acc[i][0] = fma2(gv, s02, acc[i][0]);
                acc[i][1] = fma2(gv, s12, acc[i][1]);
            }
        }
        __syncthreads();
        float* sp = Sst + ((size_t)(bh * 15 + ck) * 4 + cg) * 4096;
#pragma unroll
        for (int i = 0; i < 4; i++) {
            int r0 = tr * 8 + 2 * i;
            float x0, x1, y0, y1;
            up2(acc[i][0], x0, x1);
            up2(acc[i][1], y0, y1);
            float v00 = x0 + Bin[gb + (size_t)r0 * 128 + cg * 32 + c0];
            float v01 = y0 + Bin[gb + (size_t)r0 * 128 + cg * 32 + c0 + 1];
            float v10 = x1 + Bin[gb + (size_t)(r0 + 1) * 128 + cg * 32 + c0];
            float v11 = y1 + Bin[gb + (size_t)(r0 + 1) * 128 + cg * 32 + c0 + 1];
            Ssm[r0 * 33 + c0]           = v00;
            Ssm[r0 * 33 + c0 + 1]       = v01;
            Ssm[(r0 + 1) * 33 + c0]     = v10;
            Ssm[(r0 + 1) * 33 + c0 + 1] = v11;
            sp[r0 * 32 + c0]           = v00;
            sp[r0 * 32 + c0 + 1]       = v01;
            sp[(r0 + 1) * 32 + c0]     = v10;
            sp[(r0 + 1) * 32 + c0 + 1] = v11;
        }
        __syncthreads();
    }
}

// ---------------------------------------------------------------------------
// Stitch B: parallel apply. Grid (15, 4 cg, 32 bh), 256 thr.
// ---------------------------------------------------------------------------
__global__ void __launch_bounds__(256)
stitch_apply_kernel(const float* __restrict__ qt, const float* __restrict__ Sst,
                    float* __restrict__ omid)
{
    extern __shared__ float sm[];
    float* Ssm = sm;
    float* Tq  = sm + 128 * 33;
    const int ck = blockIdx.x + 1;
    const int cg = blockIdx.y, bh = blockIdx.z;
    const int b = bh >> 4, h = bh & 15;
    const int t = threadIdx.x;
    const int tc = t & 15, tr = t >> 4;
    const int c0 = 2 * tc;

    const float* sp = Sst + ((size_t)(bh * 15 + ck - 1) * 4 + cg) * 4096;
    for (int i = t; i < 4096; i += 256) {
        int r = i >> 5, c = i & 31;
        Ssm[r * 33 + c] = sp[i];
    }
    const size_t qtb = (size_t)bh * 2048 * 128;
    for (int i = t; i < 16384; i += 256) {
        int tt = i >> 7, k = i & 127;
        Tq[k * 130 + tt] = qt[qtb + (size_t)(ck * 128 + tt) * 128 + k];
    }
    __syncthreads();

    unsigned long long acc[4][2];
#pragma unroll
    for (int i = 0; i < 4; i++) { acc[i][0] = 0ull; acc[i][1] = 0ull; }
    for (int k = 0; k < 128; k++) {
        const unsigned long long* tp =
            (const unsigned long long*)&Tq[k * 130 + tr * 8];
        float sa = Ssm[k * 33 + c0], sb = Ssm[k * 33 + c0 + 1];
        unsigned long long s02 = pk2(sa, sa), s12 = pk2(sb, sb);
#pragma unroll
        for (int i = 0; i < 4; i++) {
            unsigned long long qv = tp[i];
            acc[i][0] = fma2(qv, s02, acc[i][0]);
            acc[i][1] = fma2(qv, s12, acc[i][1]);
        }
    }
#pragma unroll
    for (int i = 0; i < 4; i++) {
        float x0, x1, y0, y1;
        up2(acc[i][0], x0, x1);
        up2(acc[i][1], y0, y1);
        int tt0 = tr * 8 + 2 * i;
        size_t r0 = ((size_t)(b * 2048 + ck * 128 + tt0)) * HID
                    + h * 128 + cg * 32 + c0;
        omid[r0]           += x0;
        omid[r0 + 1]       += y0;
        omid[r0 + HID]     += x1;
        omid[r0 + HID + 1] += y1;
    }
}

// ---------------------------------------------------------------------------
__global__ void __launch_bounds__(256)
gate_norm_kernel(float* __restrict__ o, const float* __restrict__ g,
                 const float* __restrict__ onw)
{
    const int gw = blockIdx.x * 8 + (threadIdx.x >> 5);
    const int lane = threadIdx.x & 31;
    const size_t base = (size_t)gw * 128 + lane * 4;

    float4 ov = *(float4*)&o[base];
    float ss = ov.x * ov.x + ov.y * ov.y + ov.z * ov.z + ov.w * ov.w;
#pragma unroll
    for (int m = 16; m; m >>= 1) ss += __shfl_xor_sync(0xffffffffu, ss, m);
    const float r = rsqrtf(ss * (1.f / 128.f) + 1e-5f);

    float4 gv = *(const float4*)&g[base];
    float4 wv = *(const float4*)&onw[lane * 4];
    float4 res;
    res.x = ov.x * r * wv.x * (gv.x / (1.f + expf(-gv.x)));
    res.y = ov.y * r * wv.y * (gv.y / (1.f + expf(-gv.y)));
    res.z = ov.z * r * wv.z * (gv.z / (1.f + expf(-gv.z)));
    res.w = ov.w * r * wv.w * (gv.w / (1.f + expf(-gv.w)));
    *(float4*)&o[base] = res;
}

// ---------------------------------------------------------------------------
extern "C" void kernel_launch(void* const* d_in, const int* in_sizes, int n_in,
                              void* d_out, int out_size)
{
    const float* x    = (const float*)d_in[0];
    const float* qkvw = (const float*)d_in[1];
    const float* gw   = (const float*)d_in[2];
    const float* bw   = (const float*)d_in[3];
    const float* gkw  = (const float*)d_in[4];
    const float* cw   = (const float*)d_in[5];
    const float* onw  = (const float*)d_in[6];
    const float* ow   = (const float*)d_in[7];
    float* out = (float*)d_out;

    float *qkvb, *convb, *gbuf, *omid, *al, *be, *qtb, *Gb, *Bb, *Sstb;
    __nv_bfloat16 *a3x, *a3o, *b3a, *b3o;
    cudaGetSymbolAddress((void**)&qkvb,  g_qkv);
    cudaGetSymbolAddress((void**)&convb, g_conv);
    cudaGetSymbolAddress((void**)&gbuf,  g_gbuf);
    cudaGetSymbolAddress((void**)&omid,  g_omid);
    cudaGetSymbolAddress((void**)&al,    g_alpha);
    cudaGetSymbolAddress((void**)&be,    g_beta);
    cudaGetSymbolAddress((void**)&qtb,   g_qt);
    cudaGetSymbolAddress((void**)&Gb,    g_G);
    cudaGetSymbolAddress((void**)&Bb,    g_B);
    cudaGetSymbolAddress((void**)&Sstb,  g_Sst);
    cudaGetSymbolAddress((void**)&a3x,   g_a3x);
    cudaGetSymbolAddress((void**)&a3o,   g_a3o);
    cudaGetSymbolAddress((void**)&b3a,   g_b3a);
    cudaGetSymbolAddress((void**)&b3o,   g_b3o);

    cudaFuncSetAttribute(gemm_main,
                         cudaFuncAttributeMaxDynamicSharedMemorySize, GEMM_SMEM);
    cudaFuncSetAttribute(stitch_chain_kernel,
                         cudaFuncAttributeMaxDynamicSharedMemorySize, CHAIN_SMEM);
    cudaFuncSetAttribute(stitch_apply_kernel,
                         cudaFuncAttributeMaxDynamicSharedMemorySize, CHAIN_SMEM);

    // conversions (x + 3 weights, one launch)
    convert_all<<<((BS_TOTAL + QKVD + 2 * HID) * 512 + 255) / 256, 256>>>(
        x, a3x, qkvw, b3a, gw, b3a + (size_t)QKVD * KSPLIT, ow, b3o);
    // fused qkv+g GEMM
    gemm_main<<<dim3(NFUSED / BN, BS_TOTAL / BM), 256, GEMM_SMEM>>>(
        a3x, b3a, x, qkvw, qkvb, gbuf, BS_TOTAL, NFUSED, KSPLIT, HID, QKVD);
    // alpha/beta + conv (separate, static-smem kernels)
    proj_ab_kernel<<<BS_TOTAL / 4, 256>>>(x, gkw, bw, al, be);
    conv_norm_kernel<<<BS_TOTAL, 256>>>(qkvb, cw, convb);
    // recurrence (128-thread, padded smem, dead-work pruned)
    recur_chunk_kernel<<<dim3(4, NCHUNK, 32), 128>>>(convb, al, be, omid,
                                                     qtb, Gb, Bb);
    // stitch
    stitch_chain_kernel<<<dim3(4, 32), 256, CHAIN_SMEM>>>(Gb, Bb, Sstb);
    stitch_apply_kernel<<<dim3(15, 4, 32), 256, CHAIN_SMEM>>>(qtb, Sstb, omid);
    // gated RMSNorm + output path
    gate_norm_kernel<<<BS_TOTAL * NH / 8, 256>>>(omid, gbuf, onw);
    convert_split<<<(BS_TOTAL * 512 + 255) / 256, 256>>>(omid, a3o, BS_TOTAL * 512, 0);
    gemm_main<<<dim3(HID / BN, BS_TOTAL / BM), 256, GEMM_SMEM>>>(
        a3o, b3o, omid, ow, out, out, BS_TOTAL, HID, KSPLIT, HID, HID);
}

// round 17
// speedup vs baseline: 1.2078x; 1.0932x over previous
#include <cuda_runtime.h>
#include <cuda_bf16.h>
#include <math.h>
#include <stdint.h>

// ---------------------------------------------------------------------------
// GatedDeltaNet forward. tcgen05 bf16-split GEMMs (BM=256, 3-stage cp.async,
// fused qkv+g launch), chunked delta-rule recurrence (128-thread 4-loop,
// padded conflict-free smem), split stitch, gate-norm fused with output
// bf16-split conversion. B=2, S=2048, HID=2048, H=16, HKV=4, DK=DV=128.
// ---------------------------------------------------------------------------

#if defined(__CUDA_ARCH__) && !defined(__CUDA_ARCH_FEAT_SM103_ALL)
#define NO_TCGEN05 1
#endif

#define BS_TOTAL 4096
#define HID 2048
#define QKVD 3072
#define NH 16
#define KSPLIT 6144
#define NCHUNK 16
#define CLEN 128
#define NFUSED 5120          // QKVD + HID

// ---------------- scratch (device globals; no runtime allocation) ----------
__device__ float g_qkv [ (size_t)BS_TOTAL * QKVD ];
__device__ float g_conv[ (size_t)BS_TOTAL * QKVD ];
__device__ float g_gbuf[ (size_t)BS_TOTAL * HID  ];
__device__ float g_omid[ (size_t)BS_TOTAL * HID  ];
__device__ float g_alpha[ BS_TOTAL * NH ];
__device__ float g_beta [ BS_TOTAL * NH ];
__device__ float g_qt  [ (size_t)32 * 2048 * 128 ];
__device__ float g_G   [ (size_t)32 * NCHUNK * 128 * 128 ];
__device__ float g_B   [ (size_t)32 * NCHUNK * 128 * 128 ];
__device__ float g_Sst [ (size_t)32 * 15 * 4 * 4096 ];
__device__ __nv_bfloat16 g_a3x [ (size_t)BS_TOTAL * KSPLIT ];
__device__ __nv_bfloat16 g_a3o [ (size_t)BS_TOTAL * KSPLIT ];
__device__ __nv_bfloat16 g_b3a [ (size_t)NFUSED   * KSPLIT ];
__device__ __nv_bfloat16 g_b3o [ (size_t)HID      * KSPLIT ];

// ---------------- f32x2 packed helpers -------------------------------------
__device__ __forceinline__ unsigned long long pk2(float lo, float hi) {
    unsigned long long r;
    asm("mov.b64 %0, {%1, %2};" : "=l"(r)
        : "r"(__float_as_uint(lo)), "r"(__float_as_uint(hi)));
    return r;
}
__device__ __forceinline__ void up2(unsigned long long v, float& lo, float& hi) {
    unsigned int a, b;
    asm("mov.b64 {%0, %1}, %2;" : "=r"(a), "=r"(b) : "l"(v));
    lo = __uint_as_float(a); hi = __uint_as_float(b);
}
__device__ __forceinline__ unsigned long long fma2(unsigned long long a,
                                                   unsigned long long b,
                                                   unsigned long long c) {
    unsigned long long d;
    asm("fma.rn.f32x2 %0, %1, %2, %3;" : "=l"(d) : "l"(a), "l"(b), "l"(c));
    return d;
}
__device__ __forceinline__ unsigned long long mul2(unsigned long long a,
                                                   unsigned long long b) {
    unsigned long long d;
    asm("mul.rn.f32x2 %0, %1, %2;" : "=l"(d) : "l"(a), "l"(b));
    return d;
}

// ---------------- common helpers -------------------------------------------
__device__ __forceinline__ uint32_t smem_u32(const void* p) {
    uint32_t a;
    asm("{ .reg .u64 t; cvta.to.shared.u64 t, %1; cvt.u32.u64 %0, t; }"
        : "=r"(a) : "l"(p));
    return a;
}

#define SW128(o) ((o) ^ (((o) >> 3) & 0x70))

#define CP_ASYNC16(sa, g) \
    asm volatile("cp.async.cg.shared.global [%0], [%1], 16;" \
                 :: "r"(sa), "l"(g) : "memory")
#define CP_COMMIT() asm volatile("cp.async.commit_group;" ::: "memory")
#define CP_WAIT(n)  asm volatile("cp.async.wait_group %0;" :: "n"(n) : "memory")

#ifndef NO_TCGEN05
__device__ __forceinline__ bool elect1() {
    uint32_t p;
    asm volatile("{ .reg .pred p; elect.sync _|p, 0xFFFFFFFF; selp.b32 %0,1,0,p; }"
                 : "=r"(p));
    return p != 0;
}
#define MBAR_INIT(a, c) \
    asm volatile("mbarrier.init.shared.b64 [%0], %1;" :: "r"(a), "r"(c) : "memory")
#define MBAR_WAIT(a, ph) do {                                                   \
    uint32_t _m = (a); uint32_t _p = (ph); uint32_t _d;                         \
    asm volatile("{\n\t.reg .pred p;\n\t"                                       \
        "mbarrier.try_wait.parity.acquire.cta.shared::cta.b64 p, [%1], %2;\n\t" \
        "selp.b32 %0, 1, 0, p;\n\t}"                                            \
        : "=r"(_d) : "r"(_m), "r"(_p) : "memory");                              \
    if (!_d) {                                                                  \
        asm volatile("{\n\t.reg .pred P1;\n\t"                                  \
            "WL_%=:\n\t"                                                        \
            "mbarrier.try_wait.parity.acquire.cta.shared::cta.b64 P1, [%0], %1, 0x989680;\n\t" \
            "@P1 bra.uni WD_%=;\n\t"                                            \
            "bra.uni WL_%=;\n\t"                                                \
            "WD_%=:\n\t}"                                                       \
            :: "r"(_m), "r"(_p) : "memory");                                    \
    }                                                                           \
} while (0)

#define TM_ALLOC(sa, n) \
    asm volatile("tcgen05.alloc.cta_group::1.sync.aligned.shared::cta.b32 [%0], %1;" \
                 :: "r"(sa), "r"(n) : "memory")
#define TM_DEALLOC(t, n) \
    asm volatile("tcgen05.dealloc.cta_group::1.sync.aligned.b32 %0, %1;" :: "r"(t), "r"(n))
#define TM_COMMIT(mb) \
    asm volatile("tcgen05.commit.cta_group::1.mbarrier::arrive::one.shared::cluster.b64 [%0];" \
                 :: "r"(mb) : "memory")
#define FENCE_ASYNC() asm volatile("fence.proxy.async.shared::cta;" ::: "memory")
#define TM_FENCE_AFTER() asm volatile("tcgen05.fence::after_thread_sync;" ::: "memory")
#define TM_WAIT_LD() asm volatile("tcgen05.wait::ld.sync.aligned;" ::: "memory")

__device__ __forceinline__ void mma_f16_ss(uint32_t d, uint64_t ad, uint64_t bd,
                                           uint32_t idesc, bool acc) {
    uint32_t en = acc ? 1u : 0u, z = 0u;
    asm volatile("{\n\t.reg .pred p;\n\tsetp.ne.u32 p, %5, 0;\n\t"
        "tcgen05.mma.cta_group::1.kind::f16 [%0], %1, %2, %3, {%4, %4, %4, %4}, p;\n\t}"
        :: "r"(d), "l"(ad), "l"(bd), "r"(idesc), "r"(z), "r"(en) : "memory");
}

#define LDTM_X32(r, a) \
    asm volatile("tcgen05.ld.sync.aligned.32x32b.x32.b32 "                      \
        "{%0, %1, %2, %3, %4, %5, %6, %7, "                                     \
        " %8, %9, %10, %11, %12, %13, %14, %15, "                               \
        " %16, %17, %18, %19, %20, %21, %22, %23, "                             \
        " %24, %25, %26, %27, %28, %29, %30, %31}, [%32];"                      \
        : "=r"((r)[0]),  "=r"((r)[1]),  "=r"((r)[2]),  "=r"((r)[3]),            \
          "=r"((r)[4]),  "=r"((r)[5]),  "=r"((r)[6]),  "=r"((r)[7]),            \
          "=r"((r)[8]),  "=r"((r)[9]),  "=r"((r)[10]), "=r"((r)[11]),           \
          "=r"((r)[12]), "=r"((r)[13]), "=r"((r)[14]), "=r"((r)[15]),           \
          "=r"((r)[16]), "=r"((r)[17]), "=r"((r)[18]), "=r"((r)[19]),           \
          "=r"((r)[20]), "=r"((r)[21]), "=r"((r)[22]), "=r"((r)[23]),           \
          "=r"((r)[24]), "=r"((r)[25]), "=r"((r)[26]), "=r"((r)[27]),           \
          "=r"((r)[28]), "=r"((r)[29]), "=r"((r)[30]), "=r"((r)[31])            \
        : "r"(a))
#endif // !NO_TCGEN05

// ---------------------------------------------------------------------------
// Split conversion helper.
// ---------------------------------------------------------------------------
__device__ __forceinline__ void split_row4(const float* in, __nv_bfloat16* out,
                                           int idx, int mode)
{
    int r = idx >> 9, c4 = idx & 511;
    float4 v = ((const float4*)in)[idx];
    __nv_bfloat16 h0 = __float2bfloat16_rn(v.x);
    __nv_bfloat16 h1 = __float2bfloat16_rn(v.y);
    __nv_bfloat16 h2 = __float2bfloat16_rn(v.z);
    __nv_bfloat16 h3 = __float2bfloat16_rn(v.w);
    __nv_bfloat16 l0 = __float2bfloat16_rn(v.x - __bfloat162float(h0));
    __nv_bfloat16 l1 = __float2bfloat16_rn(v.y - __bfloat162float(h1));
    __nv_bfloat16 l2 = __float2bfloat16_rn(v.z - __bfloat162float(h2));
    __nv_bfloat16 l3 = __float2bfloat16_rn(v.w - __bfloat162float(h3));
    uint2 hv, lv;
    hv.x = (uint32_t)__bfloat16_as_ushort(h0) | ((uint32_t)__bfloat16_as_ushort(h1) << 16);
    hv.y = (uint32_t)__bfloat16_as_ushort(h2) | ((uint32_t)__bfloat16_as_ushort(h3) << 16);
    lv.x = (uint32_t)__bfloat16_as_ushort(l0) | ((uint32_t)__bfloat16_as_ushort(l1) << 16);
    lv.y = (uint32_t)__bfloat16_as_ushort(l2) | ((uint32_t)__bfloat16_as_ushort(l3) << 16);
    size_t base = (size_t)r * KSPLIT + c4 * 4;
    *(uint2*)&out[base] = hv;
    if (mode == 0) {
        *(uint2*)&out[base + 2048] = hv;
        *(uint2*)&out[base + 4096] = lv;
    } else {
        *(uint2*)&out[base + 2048] = lv;
        *(uint2*)&out[base + 4096] = hv;
    }
}

__global__ void __launch_bounds__(256)
convert_split(const float* __restrict__ in, __nv_bfloat16* __restrict__ out,
              int total4, int mode)
{
    int idx = blockIdx.x * 256 + threadIdx.x;
    if (idx < total4) split_row4(in, out, idx, mode);
}

// three weight tensors in one launch (rows: 3072 qkvw | 2048 gw | 2048 ow)
__global__ void __launch_bounds__(256)
convert_weights(const float* __restrict__ qkvw, __nv_bfloat16* __restrict__ bq,
                const float* __restrict__ gw, __nv_bfloat16* __restrict__ bg,
                const float* __restrict__ ow, __nv_bfloat16* __restrict__ bo)
{
    int idx = blockIdx.x * 256 + threadIdx.x;
    if (idx < QKVD * 512)
        split_row4(qkvw, bq, idx, 1);
    else if (idx < (QKVD + HID) * 512)
        split_row4(gw, bg, idx - QKVD * 512, 1);
    else if (idx < (QKVD + 2 * HID) * 512)
        split_row4(ow, bo, idx - (QKVD + HID) * 512, 1);
}

// ---------------------------------------------------------------------------
// Main GEMM: BM=256, BN=256, BK=64, 3-stage cp.async, 1 CTA/SM.
// Epilogue routes columns < Nsplit -> C (ld=Nsplit), >= Nsplit -> C2.
// ---------------------------------------------------------------------------
#define BM 256
#define BN 256
#define BK 64
#define NSTAGE 3
#define STAGE_BYTES 65536
#define GEMM_SMEM (1024 + NSTAGE*STAGE_BYTES)

__global__ void __launch_bounds__(256, 1) __cluster_dims__(1, 1, 1)
gemm_main(const __nv_bfloat16* __restrict__ A3, const __nv_bfloat16* __restrict__ B3,
          const float* __restrict__ Af, const float* __restrict__ Bf,
          float* __restrict__ C, float* __restrict__ C2,
          int M, int N, int K3, int Kf, int Nsplit)
{
    extern __shared__ char smem[];
#ifndef NO_TCGEN05
    const uint32_t sbase = smem_u32(smem);
    const int tid = threadIdx.x;
    const int wid = tid >> 5, lane = tid & 31;
    const int bm = blockIdx.y * BM, bn = blockIdx.x * BN;

    const uint32_t IDESC =
        (1u << 4) | (1u << 7) | (1u << 10) | ((BN / 8) << 17) | ((128 / 16) << 24);
    const unsigned long long DESC_BASE =
        (2ull << 61) | (1ull << 46) | (64ull << 32) | (1ull << 16);

    if (wid == 0) TM_ALLOC(sbase + 0, 512);
    if (tid == 0) {
        MBAR_INIT(sbase + 8, 1);  MBAR_INIT(sbase + 16, 1);
        MBAR_INIT(sbase + 24, 1);
    }
    __syncthreads();
    uint32_t tmem;
    asm volatile("ld.shared.b32 %0, [%1];" : "=r"(tmem) : "r"(sbase + 0));

    const int NK = K3 / BK;
    const __nv_bfloat16* Ab = A3 + (size_t)bm * K3;
    const __nv_bfloat16* Bb = B3 + (size_t)bn * K3;

    auto load_stage = [&](int kt, int s) {
        const uint32_t sa = sbase + 1024 + s * STAGE_BYTES;
        const __nv_bfloat16* Ak = Ab + (size_t)kt * BK;
#pragma unroll
        for (int i = 0; i < 8; i++) {
            int chunk = tid + 256 * i;
            int row = chunk >> 3, c = chunk & 7;
            CP_ASYNC16(sa + SW128(row * 128 + c * 16),
                       Ak + (size_t)row * K3 + c * 8);
        }
        const __nv_bfloat16* Bk = Bb + (size_t)kt * BK;
        const uint32_t sb = sa + 32768;
#pragma unroll
        for (int i = 0; i < 8; i++) {
            int chunk = tid + 256 * i;
            int row = chunk >> 3, c = chunk & 7;
            CP_ASYNC16(sb + SW128(row * 128 + c * 16),
                       Bk + (size_t)row * K3 + c * 8);
        }
    };

    load_stage(0, 0); CP_COMMIT();
    load_stage(1, 1); CP_COMMIT();

    int ph[NSTAGE] = {0, 0, 0};
    int sidx = 0;
    for (int kt = 0; kt < NK; kt++) {
        const int s = sidx;
        CP_WAIT(1);
        __syncthreads();
        if (wid == 0) {
            FENCE_ASYNC();
            if (elect1()) {
                const uint32_t st = sbase + 1024 + s * STAGE_BYTES;
                uint64_t ad = DESC_BASE | ((st >> 4) & 0x3FFF);
                uint64_t bd = DESC_BASE | (((st + 32768) >> 4) & 0x3FFF);
#pragma unroll
                for (int half = 0; half < 2; half++)
#pragma unroll
                    for (int kc = 0; kc < 4; kc++)
                        mma_f16_ss(tmem + half * 256,
                                   ad + half * 1024 + kc * 2, bd + kc * 2,
                                   IDESC, (kt > 0) || (kc > 0));
                TM_COMMIT(sbase + 8 + s * 8);
            }
        }
        const int kn = kt + 2;
        if (kn < NK) {
            int sp = s + 2; if (sp >= NSTAGE) sp -= NSTAGE;
            if (kt >= 1) {
                MBAR_WAIT(sbase + 8 + sp * 8, ph[sp]);
                ph[sp] ^= 1;
            }
            load_stage(kn, sp);
            CP_COMMIT();
        }
        sidx = s + 1; if (sidx >= NSTAGE) sidx -= NSTAGE;
    }
    {
        int sl = (NK - 1) % NSTAGE;
        MBAR_WAIT(sbase + 8 + sl * 8, ph[sl]);
    }
    TM_FENCE_AFTER();

    {
        const int sub = wid & 3, half = wid >> 2;
        const int gc0 = bn + half * 128;
        float* base; int ld, coff;
        if (gc0 < Nsplit) { base = C;  ld = Nsplit;     coff = gc0; }
        else              { base = C2; ld = N - Nsplit; coff = gc0 - Nsplit; }
#pragma unroll
        for (int mh = 0; mh < 2; mh++) {
            const int row = bm + mh * 128 + sub * 32 + lane;
            float* crow = base + (size_t)row * ld + coff;
#pragma unroll
            for (int cb = 0; cb < 4; cb++) {
                uint32_t r[32];
                LDTM_X32(r, tmem + mh * 256 + half * 128 + cb * 32);
                TM_WAIT_LD();
#pragma unroll
                for (int j = 0; j < 8; j++) {
                    float4 o = make_float4(__uint_as_float(r[4 * j + 0]),
                                           __uint_as_float(r[4 * j + 1]),
                                           __uint_as_float(r[4 * j + 2]),
                                           __uint_as_float(r[4 * j + 3]));
                    *(float4*)(crow + cb * 32 + 4 * j) = o;
                }
            }
        }
    }
    __syncthreads();
    if (wid == 0) TM_DEALLOC(tmem, 512);

#else  // ---------------- fp32 f32x2 fallback (non-'a' pass) ----------------
    float* As = (float*)smem;
    float* Bs = As + 2 * 16 * 132;
    const int tid = threadIdx.x;
    const int tx = tid & 15, ty = tid >> 4;
    const int lr = tid >> 2, lk = (tid & 3) * 4;
    const int K = Kf;
    const size_t rowK64 = (size_t)64 * K;

    for (int sub = 0; sub < 4; sub++) {
        const int bm = blockIdx.y * BM + (sub >> 1) * 128;
        const int bn = blockIdx.x * BN + (sub & 1) * 128;
        const float* Aptr = Af + (size_t)(bm + lr) * K + lk;
        const float* Bptr = Bf + (size_t)(bn + lr) * K + lk;
        float* cbase; int ld, coff;
        if (bn < Nsplit) { cbase = C;  ld = Nsplit;     coff = bn; }
        else             { cbase = C2; ld = N - Nsplit; coff = bn - Nsplit; }

        unsigned long long acc[8][4];
#pragma unroll
        for (int i = 0; i < 8; i++)
#pragma unroll
            for (int j = 0; j < 4; j++) acc[i][j] = 0ull;

        float4 a0 = *(const float4*)(Aptr);
        float4 a1 = *(const float4*)(Aptr + rowK64);
        float4 b0 = *(const float4*)(Bptr);
        float4 b1 = *(const float4*)(Bptr + rowK64);
        int buf = 0;
#define AS(b,k,i) As[((b)*16 + (k)) * 132 + (i)]
#define BS(b,k,i) Bs[((b)*16 + (k)) * 132 + (i)]
        AS(buf,lk+0,lr)=a0.x; AS(buf,lk+1,lr)=a0.y; AS(buf,lk+2,lr)=a0.z; AS(buf,lk+3,lr)=a0.w;
        AS(buf,lk+0,lr+64)=a1.x; AS(buf,lk+1,lr+64)=a1.y; AS(buf,lk+2,lr+64)=a1.z; AS(buf,lk+3,lr+64)=a1.w;
        BS(buf,lk+0,lr)=b0.x; BS(buf,lk+1,lr)=b0.y; BS(buf,lk+2,lr)=b0.z; BS(buf,lk+3,lr)=b0.w;
        BS(buf,lk+0,lr+64)=b1.x; BS(buf,lk+1,lr+64)=b1.y; BS(buf,lk+2,lr+64)=b1.z; BS(buf,lk+3,lr+64)=b1.w;
        __syncthreads();

        const int nk = K >> 4;
        for (int kt = 0; kt < nk; kt++) {
            const bool hasNext = (kt + 1) < nk;
            float4 na0, na1, nb0, nb1;
            if (hasNext) {
                const float* Ap = Aptr + (size_t)(kt + 1) * 16;
                const float* Bp = Bptr + (size_t)(kt + 1) * 16;
                na0 = *(const float4*)(Ap);  na1 = *(const float4*)(Ap + rowK64);
                nb0 = *(const float4*)(Bp);  nb1 = *(const float4*)(Bp + rowK64);
            }
#pragma unroll
            for (int kk = 0; kk < 16; kk++) {
                float4 af0 = *(const float4*)&AS(buf, kk, ty * 8);
                float4 af1 = *(const float4*)&AS(buf, kk, ty * 8 + 4);
                ulonglong2 bp0 = *(const ulonglong2*)&BS(buf, kk, tx * 8);
                ulonglong2 bp1 = *(const ulonglong2*)&BS(buf, kk, tx * 8 + 4);
                unsigned long long bb[4] = { bp0.x, bp0.y, bp1.x, bp1.y };
                unsigned long long a2[8];
                a2[0]=pk2(af0.x,af0.x); a2[1]=pk2(af0.y,af0.y);
                a2[2]=pk2(af0.z,af0.z); a2[3]=pk2(af0.w,af0.w);
                a2[4]=pk2(af1.x,af1.x); a2[5]=pk2(af1.y,af1.y);
                a2[6]=pk2(af1.z,af1.z); a2[7]=pk2(af1.w,af1.w);
#pragma unroll
                for (int i = 0; i < 8; i++) {
                    acc[i][0] = fma2(a2[i], bb[0], acc[i][0]);
                    acc[i][1] = fma2(a2[i], bb[1], acc[i][1]);
                    acc[i][2] = fma2(a2[i], bb[2], acc[i][2]);
                    acc[i][3] = fma2(a2[i], bb[3], acc[i][3]);
                }
            }
            if (hasNext) {
                buf ^= 1;
                __syncthreads();
                AS(buf,lk+0,lr)=na0.x; AS(buf,lk+1,lr)=na0.y; AS(buf,lk+2,lr)=na0.z; AS(buf,lk+3,lr)=na0.w;
                AS(buf,lk+0,lr+64)=na1.x; AS(buf,lk+1,lr+64)=na1.y; AS(buf,lk+2,lr+64)=na1.z; AS(buf,lk+3,lr+64)=na1.w;
                BS(buf,lk+0,lr)=nb0.x; BS(buf,lk+1,lr)=nb0.y; BS(buf,lk+2,lr)=nb0.z; BS(buf,lk+3,lr)=nb0.w;
                BS(buf,lk+0,lr+64)=nb1.x; BS(buf,lk+1,lr+64)=nb1.y; BS(buf,lk+2,lr+64)=nb1.z; BS(buf,lk+3,lr+64)=nb1.w;
                __syncthreads();
            }
        }
#undef AS
#undef BS
#pragma unroll
        for (int i = 0; i < 8; i++) {
            float r0,r1,r2,r3,r4,r5,r6,r7;
            up2(acc[i][0],r0,r1); up2(acc[i][1],r2,r3);
            up2(acc[i][2],r4,r5); up2(acc[i][3],r6,r7);
            float* cp = cbase + (size_t)(bm + ty * 8 + i) * ld + coff + tx * 8;
            *(float4*)(cp)     = make_float4(r0,r1,r2,r3);
            *(float4*)(cp + 4) = make_float4(r4,r5,r6,r7);
        }
        __syncthreads();
    }
#endif
}

// ---------------------------------------------------------------------------
// Causal depthwise conv (K=4) + SiLU + per-head l2norm (static smem).
// ---------------------------------------------------------------------------
__global__ void __launch_bounds__(256)
conv_norm_kernel(const float* __restrict__ qkv, const float* __restrict__ cw,
                 float* __restrict__ out)
{
    const int bs = blockIdx.x;
    const int b = bs >> 11, s = bs & 2047;
    __shared__ float buf[QKVD];
    __shared__ float sc[20];
    const size_t rowbase = (size_t)bs * QKVD;

    for (int c = threadIdx.x; c < QKVD; c += 256) {
        float acc = 0.f;
#pragma unroll
        for (int i = 0; i < 4; i++) {
            int sp = s - 3 + i;
            if (sp >= 0)
                acc += cw[c * 4 + i] * qkv[((size_t)(b * 2048 + sp)) * QKVD + c];
        }
        buf[c] = acc / (1.f + expf(-acc));
    }
    __syncthreads();

    const int w = threadIdx.x >> 5, lane = threadIdx.x & 31;
    for (int hd = w; hd < 20; hd += 8) {
        const int base = (hd < 16) ? hd * 128 : 2048 + (hd - 16) * 128;
        float ss = 0.f;
#pragma unroll
        for (int j = 0; j < 4; j++) {
            float x = buf[base + lane + 32 * j];
            ss += x * x;
        }
#pragma unroll
        for (int m = 16; m; m >>= 1) ss += __shfl_xor_sync(0xffffffffu, ss, m);
        if (lane == 0) {
            float r = rsqrtf(ss + 1e-6f);
            sc[hd] = (hd < 16) ? r * 0.08838834764831845f : r;
        }
    }
    __syncthreads();

    for (int c = threadIdx.x; c < QKVD; c += 256) {
        float scale = (c < 2048) ? sc[c >> 7]
                    : (c < 2560) ? sc[16 + ((c - 2048) >> 7)]
                                 : 1.f;
        out[rowbase + c] = buf[c] * scale;
    }
}

// ---------------------------------------------------------------------------
// alpha/beta projections, 4 bs-rows per block (static smem).
// ---------------------------------------------------------------------------
__global__ void __launch_bounds__(256)
proj_ab_kernel(const float* __restrict__ x, const float* __restrict__ gkw,
               const float* __restrict__ bw, float* __restrict__ alpha,
               float* __restrict__ beta)
{
    const int bs0 = blockIdx.x * 4;
    __shared__ __align__(16) float xs[4][HID];
    for (int i = threadIdx.x * 4; i < 4 * HID; i += 256 * 4) {
        int r = i >> 11, c = i & (HID - 1);
        *(float4*)&xs[r][c] = *(const float4*)&x[(size_t)(bs0 + r) * HID + c];
    }
    __syncthreads();

    const int w = threadIdx.x >> 5, lane = threadIdx.x & 31;
    for (int out = w; out < 32; out += 8) {
        const float* wr = (out < 16) ? gkw + (size_t)out * HID
                                     : bw + (size_t)(out - 16) * HID;
        const float4* w4 = (const float4*)wr;
        float acc0 = 0.f, acc1 = 0.f, acc2 = 0.f, acc3 = 0.f;
#pragma unroll 4
        for (int j = 0; j < 16; j++) {
            float4 q = w4[lane + 32 * j];
            float4 a0 = ((const float4*)xs[0])[lane + 32 * j];
            float4 a1 = ((const float4*)xs[1])[lane + 32 * j];
            float4 a2 = ((const float4*)xs[2])[lane + 32 * j];
            float4 a3 = ((const float4*)xs[3])[lane + 32 * j];
            acc0 += a0.x*q.x + a0.y*q.y + a0.z*q.z + a0.w*q.w;
            acc1 += a1.x*q.x + a1.y*q.y + a1.z*q.z + a1.w*q.w;
            acc2 += a2.x*q.x + a2.y*q.y + a2.z*q.z + a2.w*q.w;
            acc3 += a3.x*q.x + a3.y*q.y + a3.z*q.z + a3.w*q.w;
        }
#pragma unroll
        for (int m = 16; m; m >>= 1) {
            acc0 += __shfl_down_sync(0xffffffffu, acc0, m);
            acc1 += __shfl_down_sync(0xffffffffu, acc1, m);
            acc2 += __shfl_down_sync(0xffffffffu, acc2, m);
            acc3 += __shfl_down_sync(0xffffffffu, acc3, m);
        }
        if (lane == 0) {
            float accs[4] = {acc0, acc1, acc2, acc3};
#pragma unroll
            for (int r = 0; r < 4; r++) {
                float p = accs[r];
                int bs = bs0 + r;
                if (out < 16) {
                    float ls = fminf(p, 0.f) - log1pf(expf(-fabsf(p)));
                    alpha[bs * NH + out] = expf(ls * 0.0625f);
                } else {
                    beta[bs * NH + (out - 16)] = 1.f / (1.f + expf(-p));
                }
            }
        }
    }
}

// ---------------------------------------------------------------------------
// Chunked delta recurrence, phase 1 (R13 form: 128-thread 4-loop, padded
// conflict-free smem, no pruning guards).
// ---------------------------------------------------------------------------
__global__ void __launch_bounds__(128)
recur_chunk_kernel(const float* __restrict__ conv, const float* __restrict__ alpha,
                   const float* __restrict__ beta, float* __restrict__ omid,
                   float* __restrict__ qt, float* __restrict__ Gout,
                   float* __restrict__ Bout)
{
    const int cg = blockIdx.x;
    const int ck = blockIdx.y;
    const int bh = blockIdx.z;
    const int b = bh >> 4, h = bh & 15;
    const int t = threadIdx.x;
    const int cq = t >> 2, rg = t & 3;
    const int col = cg * 32 + cq;
    const int kh = h >> 2;
    const int woff = ((t >> 5) * 34) + (t & 31);

    __shared__ __align__(16) float kqf[4][2][136];

    unsigned long long S2[16], G2[16];
#pragma unroll
    for (int i = 0; i < 16; i++) {
        S2[i] = 0ull;
        int r0 = rg * 32 + 2 * i;
        G2[i] = pk2((r0 == col) ? 1.f : 0.f, (r0 + 1 == col) ? 1.f : 0.f);
    }

    const int s0g = ck * CLEN;
    const size_t bb0 = (size_t)b * 2048 * QKVD;
    const float* qc = conv + bb0 + (size_t)s0g * QKVD + h * 128;
    const float* kc = conv + bb0 + (size_t)s0g * QKVD + 2048 + kh * 128;
    const float* vc = conv + bb0 + (size_t)s0g * QKVD + 2560 + kh * 128 + col;
    const float* abase = alpha + (size_t)(b * 2048 + s0g) * NH + h;
    const float* bbase = beta  + (size_t)(b * 2048 + s0g) * NH + h;
    float* obase  = omid + (size_t)(b * 2048 + s0g) * HID + h * 128;
    float* qtbase = qt + ((size_t)bh * 2048 + s0g) * 128;

    kqf[0][0][woff] = kc[t];
    kqf[0][1][woff] = qc[t];
    float kst = kc[QKVD + t];
    float qst = qc[QKVD + t];
    float vA = vc[0],  vB = vc[QKVD];
    float aA = abase[0], aB = abase[NH];
    float bA = bbase[0], bB = bbase[NH];
    __syncthreads();

    for (int s = 0; s < CLEN; s++) {
        kqf[(s + 1) & 3][0][woff] = kst;
        kqf[(s + 1) & 3][1][woff] = qst;
        const int sn = (s + 2 < CLEN) ? s + 2 : CLEN - 1;
        kst = kc[(size_t)sn * QKVD + t];
        qst = qc[(size_t)sn * QKVD + t];
        float vN = vc[(size_t)sn * QKVD];
        float aN = abase[sn * NH];
        float bN = bbase[sn * NH];
        __syncthreads();

        const unsigned long long* k2 =
            (const unsigned long long*)kqf[s & 3][0] + rg * 17;
        const unsigned long long* q2 =
            (const unsigned long long*)kqf[s & 3][1] + rg * 17;
        const unsigned long long a2 = pk2(aA, aA);

        unsigned long long uA = 0ull;
#pragma unroll
        for (int i = 0; i < 16; i++) uA = fma2(k2[i], G2[i], uA);
        float ux, uy; up2(uA, ux, uy);
        float u = ux + uy;
        u += __shfl_xor_sync(0xffffffffu, u, 1);
        u += __shfl_xor_sync(0xffffffffu, u, 2);
        const float w = aA * bA * u;
        const unsigned long long w2 = pk2(-w, -w);
        unsigned long long qacc = 0ull;
#pragma unroll
        for (int i = 0; i < 16; i++) {
            unsigned long long g = mul2(G2[i], a2);
            g = fma2(k2[i], w2, g);
            G2[i] = g;
            qacc = fma2(q2[i], g, qacc);
        }
        float qx, qy; up2(qacc, qx, qy);
        float qtv = qx + qy;
        qtv += __shfl_xor_sync(0xffffffffu, qtv, 1);
        qtv += __shfl_xor_sync(0xffffffffu, qtv, 2);
        if (rg == 0) qtbase[(size_t)s * 128 + col] = qtv;

        unsigned long long vpA = 0ull;
#pragma unroll
        for (int i = 0; i < 16; i++) {
            unsigned long long sv = mul2(S2[i], a2);
            vpA = fma2(k2[i], sv, vpA);
            S2[i] = sv;
        }
        float px, py; up2(vpA, px, py);
        float vp = px + py;
        vp += __shfl_xor_sync(0xffffffffu, vp, 1);
        vp += __shfl_xor_sync(0xffffffffu, vp, 2);
        const float delta = (vA - vp) * bA;
        const unsigned long long d2 = pk2(delta, delta);

        unsigned long long oacc = 0ull;
#pragma unroll
        for (int i = 0; i < 16; i++) {
            unsigned long long sv = fma2(k2[i], d2, S2[i]);
            S2[i] = sv;
            oacc = fma2(q2[i], sv, oacc);
        }
        float ox, oy; up2(oacc, ox, oy);
        float osum = ox + oy;
        osum += __shfl_xor_sync(0xffffffffu, osum, 1);
        osum += __shfl_xor_sync(0xffffffffu, osum, 2);
        if (rg == 0) obase[(size_t)s * HID + col] = osum;

        vA = vB; vB = vN;
        aA = aB; aB = aN;
        bA = bB; bB = bN;
    }

    float* Gp = Gout + ((size_t)bh * NCHUNK + ck) * 16384;
    float* Bp = Bout + ((size_t)bh * NCHUNK + ck) * 16384;
#pragma unroll
    for (int i = 0; i < 16; i++) {
        int r0 = rg * 32 + 2 * i;
        float g0, g1; up2(G2[i], g0, g1);
        Gp[(size_t)r0 * 128 + col]       = g0;
        Gp[(size_t)(r0 + 1) * 128 + col] = g1;
        float s0v, s1v; up2(S2[i], s0v, s1v);
        Bp[(size_t)r0 * 128 + col]       = s0v;
        Bp[(size_t)(r0 + 1) * 128 + col] = s1v;
    }
}

// ---------------------------------------------------------------------------
// Stitch A: serial S_start chain. Grid (4 cg, 32 bh), 256 thr.
// ---------------------------------------------------------------------------
#define CHAIN_SMEM (128*33*4 + 128*130*4)

__global__ void __launch_bounds__(256)
stitch_chain_kernel(const float* __restrict__ Gin, const float* __restrict__ Bin,
                    float* __restrict__ Sst)
{
    extern __shared__ float sm[];
    float* Ssm = sm;
    float* Tg  = sm + 128 * 33;
    const int cg = blockIdx.x, bh = blockIdx.y;
    const int t = threadIdx.x;
    const int tc = t & 15, tr = t >> 4;
    const int c0 = 2 * tc;
    const size_t gb0 = (size_t)bh * NCHUNK * 16384;

    for (int i = t; i < 4096; i += 256) {
        int r = i >> 5, c = i & 31;
        float v = Bin[gb0 + (size_t)r * 128 + cg * 32 + c];
        Ssm[r * 33 + c] = v;
        Sst[((size_t)(bh * 15 + 0) * 4 + cg) * 4096 + i] = v;
    }
    __syncthreads();

    for (int ck = 1; ck < NCHUNK - 1; ck++) {
        const size_t gb = gb0 + (size_t)ck * 16384;
        for (int i = t; i < 16384; i += 256) {
            int r = i >> 7, k = i & 127;
            Tg[k * 130 + r] = Gin[gb + i];
        }
        __syncthreads();
        unsigned long long acc[4][2];
#pragma unroll
        for (int i = 0; i < 4; i++) { acc[i][0] = 0ull; acc[i][1] = 0ull; }
        for (int k = 0; k < 128; k++) {
            const unsigned long long* gp =
                (const unsigned long long*)&Tg[k * 130 + tr * 8];
            float sa = Ssm[k * 33 + c0], sb = Ssm[k * 33 + c0 + 1];
            unsigned long long s02 = pk2(sa, sa), s12 = pk2(sb, sb);
#pragma unroll
            for (int i = 0; i < 4; i++) {
                unsigned long long gv = gp[i];
                acc[i][0] = fma2(gv, s02, acc[i][0]);
                acc[i][1] = fma2(gv, s12, acc[i][1]);
            }
        }
        __syncthreads();
        float* sp = Sst + ((size_t)(bh * 15 + ck) * 4 + cg) * 4096;
#pragma unroll
        for (int i = 0; i < 4; i++) {
            int r0 = tr * 8 + 2 * i;
            float x0, x1, y0, y1;
            up2(acc[i][0], x0, x1);
            up2(acc[i][1], y0, y1);
            float v00 = x0 + Bin[gb + (size_t)r0 * 128 + cg * 32 + c0];
            float v01 = y0 + Bin[gb + (size_t)r0 * 128 + cg * 32 + c0 + 1];
            float v10 = x1 + Bin[gb + (size_t)(r0 + 1) * 128 + cg * 32 + c0];
            float v11 = y1 + Bin[gb + (size_t)(r0 + 1) * 128 + cg * 32 + c0 + 1];
            Ssm[r0 * 33 + c0]           = v00;
            Ssm[r0 * 33 + c0 + 1]       = v01;
            Ssm[(r0 + 1) * 33 + c0]     = v10;
            Ssm[(r0 + 1) * 33 + c0 + 1] = v11;
            sp[r0 * 32 + c0]           = v00;
            sp[r0 * 32 + c0 + 1]       = v01;
            sp[(r0 + 1) * 32 + c0]     = v10;
            sp[(r0 + 1) * 32 + c0 + 1] = v11;
        }
        __syncthreads();
    }
}

// ---------------------------------------------------------------------------
// Stitch B: parallel apply. Grid (15, 4 cg, 32 bh), 256 thr.
// ---------------------------------------------------------------------------
__global__ void __launch_bounds__(256)
stitch_apply_kernel(const float* __restrict__ qt, const float* __restrict__ Sst,
                    float* __restrict__ omid)
{
    extern __shared__ float sm[];
    float* Ssm = sm;
    float* Tq  = sm + 128 * 33;
    const int ck = blockIdx.x + 1;
    const int cg = blockIdx.y, bh = blockIdx.z;
    const int b = bh >> 4, h = bh & 15;
    const int t = threadIdx.x;
    const int tc = t & 15, tr = t >> 4;
    const int c0 = 2 * tc;

    const float* sp = Sst + ((size_t)(bh * 15 + ck - 1) * 4 + cg) * 4096;
    for (int i = t; i < 4096; i += 256) {
        int r = i >> 5, c = i & 31;
        Ssm[r * 33 + c] = sp[i];
    }
    const size_t qtb = (size_t)bh * 2048 * 128;
    for (int i = t; i < 16384; i += 256) {
        int tt = i >> 7, k = i & 127;
        Tq[k * 130 + tt] = qt[qtb + (size_t)(ck * 128 + tt) * 128 + k];
    }
    __syncthreads();

    unsigned long long acc[4][2];
#pragma unroll
    for (int i = 0; i < 4; i++) { acc[i][0] = 0ull; acc[i][1] = 0ull; }
    for (int k = 0; k < 128; k++) {
        const unsigned long long* tp =
            (const unsigned long long*)&Tq[k * 130 + tr * 8];
        float sa = Ssm[k * 33 + c0], sb = Ssm[k * 33 + c0 + 1];
        unsigned long long s02 = pk2(sa, sa), s12 = pk2(sb, sb);
#pragma unroll
        for (int i = 0; i < 4; i++) {
            unsigned long long qv = tp[i];
            acc[i][0] = fma2(qv, s02, acc[i][0]);
            acc[i][1] = fma2(qv, s12, acc[i][1]);
        }
    }
#pragma unroll
    for (int i = 0; i < 4; i++) {
        float x0, x1, y0, y1;
        up2(acc[i][0], x0, x1);
        up2(acc[i][1], y0, y1);
        int tt0 = tr * 8 + 2 * i;
        size_t r0 = ((size_t)(b * 2048 + ck * 128 + tt0)) * HID
                    + h * 128 + cg * 32 + c0;
        omid[r0]           += x0;
        omid[r0 + 1]       += y0;
        omid[r0 + HID]     += x1;
        omid[r0 + HID + 1] += y1;
    }
}

// ---------------------------------------------------------------------------
// Gated per-head RMSNorm + SiLU gate fused with bf16 split output:
// writes a3o directly in [hi | hi | lo] layout (A-operand, mode 0).
// Warp per (bs,h); lane handles 4 consecutive columns (8B-aligned bf16x4).
// ---------------------------------------------------------------------------
__global__ void __launch_bounds__(256)
gate_norm_kernel(const float* __restrict__ o, const float* __restrict__ g,
                 const float* __restrict__ onw, __nv_bfloat16* __restrict__ a3o)
{
    const int gw = blockIdx.x * 8 + (threadIdx.x >> 5);   // bs*16 + h
    const int lane = threadIdx.x & 31;
    const size_t base = (size_t)gw * 128 + lane * 4;

    float4 ov = *(const float4*)&o[base];
    float ss = ov.x * ov.x + ov.y * ov.y + ov.z * ov.z + ov.w * ov.w;
#pragma unroll
    for (int m = 16; m; m >>= 1) ss += __shfl_xor_sync(0xffffffffu, ss, m);
    const float r = rsqrtf(ss * (1.f / 128.f) + 1e-5f);

    float4 gv = *(const float4*)&g[base];
    float4 wv = *(const float4*)&onw[lane * 4];
    float4 res;
    res.x = ov.x * r * wv.x * (gv.x / (1.f + expf(-gv.x)));
    res.y = ov.y * r * wv.y * (gv.y / (1.f + expf(-gv.y)));
    res.z = ov.z * r * wv.z * (gv.z / (1.f + expf(-gv.z)));
    res.w = ov.w * r * wv.w * (gv.w / (1.f + expf(-gv.w)));

    __nv_bfloat16 h0 = __float2bfloat16_rn(res.x);
    __nv_bfloat16 h1 = __float2bfloat16_rn(res.y);
    __nv_bfloat16 h2 = __float2bfloat16_rn(res.z);
    __nv_bfloat16 h3 = __float2bfloat16_rn(res.w);
    __nv_bfloat16 l0 = __float2bfloat16_rn(res.x - __bfloat162float(h0));
    __nv_bfloat16 l1 = __float2bfloat16_rn(res.y - __bfloat162float(h1));
    __nv_bfloat16 l2 = __float2bfloat16_rn(res.z - __bfloat162float(h2));
    __nv_bfloat16 l3 = __float2bfloat16_rn(res.w - __bfloat162float(h3));
    uint2 hv, lv;
    hv.x = (uint32_t)__bfloat16_as_ushort(h0) | ((uint32_t)__bfloat16_as_ushort(h1) << 16);
    hv.y = (uint32_t)__bfloat16_as_ushort(h2) | ((uint32_t)__bfloat16_as_ushort(h3) << 16);
    lv.x = (uint32_t)__bfloat16_as_ushort(l0) | ((uint32_t)__bfloat16_as_ushort(l1) << 16);
    lv.y = (uint32_t)__bfloat16_as_ushort(l2) | ((uint32_t)__bfloat16_as_ushort(l3) << 16);

    const int bs = gw >> 4, h = gw & 15;
    size_t ob = (size_t)bs * KSPLIT + h * 128 + lane * 4;
    *(uint2*)&a3o[ob]        = hv;
    *(uint2*)&a3o[ob + 2048] = hv;
    *(uint2*)&a3o[ob + 4096] = lv;
}

// ---------------------------------------------------------------------------
extern "C" void kernel_launch(void* const* d_in, const int* in_sizes, int n_in,
                              void* d_out, int out_size)
{
    const float* x    = (const float*)d_in[0];
    const float* qkvw = (const float*)d_in[1];
    const float* gw   = (const float*)d_in[2];
    const float* bw   = (const float*)d_in[3];
    const float* gkw  = (const float*)d_in[4];
    const float* cw   = (const float*)d_in[5];
    const float* onw  = (const float*)d_in[6];
    const float* ow   = (const float*)d_in[7];
    float* out = (float*)d_out;

    float *qkvb, *convb, *gbuf, *omid, *al, *be, *qtb, *Gb, *Bb, *Sstb;
    __nv_bfloat16 *a3x, *a3o, *b3a, *b3o;
    cudaGetSymbolAddress((void**)&qkvb,  g_qkv);
    cudaGetSymbolAddress((void**)&convb, g_conv);
    cudaGetSymbolAddress((void**)&gbuf,  g_gbuf);
    cudaGetSymbolAddress((void**)&omid,  g_omid);
    cudaGetSymbolAddress((void**)&al,    g_alpha);
    cudaGetSymbolAddress((void**)&be,    g_beta);
    cudaGetSymbolAddress((void**)&qtb,   g_qt);
    cudaGetSymbolAddress((void**)&Gb,    g_G);
    cudaGetSymbolAddress((void**)&Bb,    g_B);
    cudaGetSymbolAddress((void**)&Sstb,  g_Sst);
    cudaGetSymbolAddress((void**)&a3x,   g_a3x);
    cudaGetSymbolAddress((void**)&a3o,   g_a3o);
    cudaGetSymbolAddress((void**)&b3a,   g_b3a);
    cudaGetSymbolAddress((void**)&b3o,   g_b3o);

    cudaFuncSetAttribute(gemm_main,
                         cudaFuncAttributeMaxDynamicSharedMemorySize, GEMM_SMEM);
    cudaFuncSetAttribute(stitch_chain_kernel,
                         cudaFuncAttributeMaxDynamicSharedMemorySize, CHAIN_SMEM);
    cudaFuncSetAttribute(stitch_apply_kernel,
                         cudaFuncAttributeMaxDynamicSharedMemorySize, CHAIN_SMEM);

    // conversions (two launches, R13 form)
    convert_split<<<(BS_TOTAL * 512 + 255) / 256, 256>>>(x, a3x, BS_TOTAL * 512, 0);
    convert_weights<<<((QKVD + 2 * HID) * 512 + 255) / 256, 256>>>(
        qkvw, b3a, gw, b3a + (size_t)QKVD * KSPLIT, ow, b3o);

    // fused qkv+g GEMM (N=5120, epilogue routes at col 3072)
    gemm_main<<<dim3(NFUSED / BN, BS_TOTAL / BM), 256, GEMM_SMEM>>>(
        a3x, b3a, x, qkvw, qkvb, gbuf, BS_TOTAL, NFUSED, KSPLIT, HID, QKVD);

    proj_ab_kernel<<<BS_TOTAL / 4, 256>>>(x, gkw, bw, al, be);
    conv_norm_kernel<<<BS_TOTAL, 256>>>(qkvb, cw, convb);
    recur_chunk_kernel<<<dim3(4, NCHUNK, 32), 128>>>(convb, al, be, omid,
                                                     qtb, Gb, Bb);
    stitch_chain_kernel<<<dim3(4, 32), 256, CHAIN_SMEM>>>(Gb, Bb, Sstb);
    stitch_apply_kernel<<<dim3(15, 4, 32), 256, CHAIN_SMEM>>>(qtb, Sstb, omid);
    // gated RMSNorm fused with bf16-split conversion (writes a3o directly)
    gate_norm_kernel<<<BS_TOTAL * NH / 8, 256>>>(omid, gbuf, onw, a3o);
    // out = og @ o_w^T
    gemm_main<<<dim3(HID / BN, BS_TOTAL / BM), 256, GEMM_SMEM>>>(
        a3o, b3o, omid, ow, out, out, BS_TOTAL, HID, KSPLIT, HID, HID);
}